// round 13
// baseline (speedup 1.0000x reference)
#include <cuda_runtime.h>
#include <cuda_bf16.h>
#include <cuda_fp16.h>
#include <math.h>
#include <stdint.h>

#define B_    8
#define CIN   64
#define COUT  128
#define C2    256
#define HW    65536
#define NBLK  4096
#define EPSV  1e-5f

// ---------------- scratch ----------------
__device__ float g1buf[(size_t)NBLK * C2 * 64];
__device__ float g2buf[(size_t)NBLK * C2 * 64];
__device__ float g3buf[(size_t)NBLK * COUT * 64];

// fp16 weights (block convs), bf16 hi/lo for convc
__device__ __half w216[36 * 16384];  // [tap*4+chunk][oc 256][ic 64]
__device__ __half w116[2 * 16384];   // [chunk2][oc 256][ic 64]
__device__ __half w316[4 * 8192];    // [chunk4][oc 128][ic 64]
__device__ __nv_bfloat16 wch[8192];  // [oc 128][ic 64]
__device__ __nv_bfloat16 wcl[8192];

__device__ double d_sum0[COUT], d_sq0[COUT];
__device__ double d_sum1[C2],   d_sq1[C2];
__device__ double d_sum2[C2],   d_sq2[C2];
__device__ double d_sum3[COUT], d_sq3[COUT];
__device__ float  d_a0[COUT], d_b0[COUT];
__device__ float  d_a1[C2],   d_b1[C2];
__device__ float  d_a2[C2],   d_b2[C2];
__device__ float  d_a3[COUT], d_b3[COUT];

#define PKU(x, y) ((unsigned)(x) | ((unsigned)(y) << 16))

// ---------------- MMA helpers ----------------
__device__ __forceinline__ void mma16816(float* d, const unsigned* a, unsigned b0, unsigned b1) {
    asm volatile(
        "mma.sync.aligned.m16n8k16.row.col.f32.bf16.bf16.f32 "
        "{%0,%1,%2,%3}, {%4,%5,%6,%7}, {%8,%9}, {%0,%1,%2,%3};"
        : "+f"(d[0]), "+f"(d[1]), "+f"(d[2]), "+f"(d[3])
        : "r"(a[0]), "r"(a[1]), "r"(a[2]), "r"(a[3]), "r"(b0), "r"(b1));
}
__device__ __forceinline__ void mma16816h(float* d, const unsigned* a, unsigned b0, unsigned b1) {
    asm volatile(
        "mma.sync.aligned.m16n8k16.row.col.f32.f16.f16.f32 "
        "{%0,%1,%2,%3}, {%4,%5,%6,%7}, {%8,%9}, {%0,%1,%2,%3};"
        : "+f"(d[0]), "+f"(d[1]), "+f"(d[2]), "+f"(d[3])
        : "r"(a[0]), "r"(a[1]), "r"(a[2]), "r"(a[3]), "r"(b0), "r"(b1));
}

__device__ __forceinline__ void cp_async16(uint32_t sdst, const void* gsrc) {
    asm volatile("cp.async.cg.shared.global [%0], [%1], 16;" :: "r"(sdst), "l"(gsrc));
}
#define CP_COMMIT() asm volatile("cp.async.commit_group;" ::: "memory")
#define CP_WAIT0()  asm volatile("cp.async.wait_group 0;" ::: "memory")

__device__ __forceinline__ void quad_stats(float s, float s2, int tg,
                                           double* gsum, double* gsq) {
    s  += __shfl_xor_sync(0xffffffffu, s, 1);
    s  += __shfl_xor_sync(0xffffffffu, s, 2);
    s2 += __shfl_xor_sync(0xffffffffu, s2, 1);
    s2 += __shfl_xor_sync(0xffffffffu, s2, 2);
    if (tg == 0) { atomicAdd(gsum, (double)s); atomicAdd(gsq, (double)s2); }
}

// ---------------- utility ----------------
__global__ void zero_stats_kernel() {
    int t = threadIdx.x;
    if (t < COUT) { d_sum0[t] = 0.0; d_sq0[t] = 0.0; d_sum3[t] = 0.0; d_sq3[t] = 0.0; }
    d_sum1[t] = 0.0; d_sq1[t] = 0.0; d_sum2[t] = 0.0; d_sq2[t] = 0.0;
}

__global__ void finalize_kernel(int stage, const float* __restrict__ gamma,
                                const float* __restrict__ beta, double invN) {
    int t = threadIdx.x;
    const double *sum, *sq; float *a, *bsh; int C;
    if (stage == 0)      { sum = d_sum0; sq = d_sq0; a = d_a0; bsh = d_b0; C = COUT; }
    else if (stage == 1) { sum = d_sum1; sq = d_sq1; a = d_a1; bsh = d_b1; C = C2; }
    else if (stage == 2) { sum = d_sum2; sq = d_sq2; a = d_a2; bsh = d_b2; C = C2; }
    else                 { sum = d_sum3; sq = d_sq3; a = d_a3; bsh = d_b3; C = COUT; }
    if (t < C) {
        double mean = sum[t] * invN;
        double var  = sq[t] * invN - mean * mean;
        float v = fmaxf((float)var, 0.0f);
        float av = gamma[t] * rsqrtf(v + EPSV);
        a[t] = av;
        bsh[t] = beta[t] - av * (float)mean;
    }
}

// ---------------- weight converts ----------------
__global__ __launch_bounds__(256) void w2cvt_kernel(const float* __restrict__ w2) {
    int i4 = blockIdx.x * 256 + threadIdx.x;
    int ic0 = (i4 & 15) * 4;
    int oc  = (i4 >> 4) & 255;
    int tc  = i4 >> 12;
    int tap = tc >> 2, chunk = tc & 3;
    #pragma unroll
    for (int e = 0; e < 4; e++) {
        int ic = ic0 + e;
        float v = w2[(size_t)oc * 2304 + (chunk * 64 + ic) * 9 + tap];
        w216[(size_t)tc * 16384 + oc * 64 + ic] = __float2half(v);
    }
}

__global__ __launch_bounds__(256) void w13cvt_kernel(const float* __restrict__ w1,
                                                     const float* __restrict__ w3,
                                                     const float* __restrict__ wc) {
    int i = blockIdx.x * 256 + threadIdx.x;   // 0..16383
    {
        #pragma unroll
        for (int e = 0; e < 2; e++) {
            int idx = i * 2 + e;
            int ic = idx & 63, oc = (idx >> 6) & 255, ch = idx >> 14;
            w116[idx] = __float2half(w1[(size_t)oc * 128 + ch * 64 + ic]);
        }
    }
    {
        #pragma unroll
        for (int e = 0; e < 2; e++) {
            int idx = i * 2 + e;
            int ic = idx & 63, oc = (idx >> 6) & 127, ch = idx >> 13;
            w316[idx] = __float2half(w3[(size_t)oc * 256 + ch * 64 + ic]);
        }
    }
    if (i < 8192) {
        float v = wc[i];
        __nv_bfloat16 h = __float2bfloat16(v);
        wch[i] = h;
        wcl[i] = __float2bfloat16(v - __bfloat162float(h));
    }
}

// ---------------- convc: 1x1 64->128 via bf16 HMMA 3-pass, 64 px/CTA, fused stats ----------------
#define XCSTR  144
#define XCPART 9216
#define WCOFF  18432
#define WCPART 18432
#define SMEM_CCM (WCOFF + 2 * WCPART)
__global__ __launch_bounds__(256, 3) void convcm_kernel(const float* __restrict__ x,
                                                        const float* __restrict__ bc,
                                                        float* __restrict__ out) {
    extern __shared__ float smf[];
    char* smem = (char*)smf;
    int t = threadIdx.x, w = t >> 5, lane = t & 31;
    int g = lane >> 2, tg = lane & 3;
    int b  = blockIdx.x >> 10;
    int p0 = (blockIdx.x & 1023) << 6;
    int ocb = (w & 1) * 64;
    int pxb = (w >> 1) * 16;

    // X build: thread = (icp 32, pxg 8), 8 px x 2 ic, bf16 hi/lo packed u32
    {
        int icp = t & 31, pxg = t >> 5;
        const float* s0 = x + (((size_t)(b * CIN + icp * 2)) << 16) + p0 + pxg * 8;
        const float* s1 = s0 + HW;
        char* xb = smem + icp * 4;
        #pragma unroll
        for (int q = 0; q < 2; q++) {
            float4 u0 = ((const float4*)s0)[q];
            float4 u1 = ((const float4*)s1)[q];
            float v0[4] = {u0.x, u0.y, u0.z, u0.w};
            float v1[4] = {u1.x, u1.y, u1.z, u1.w};
            #pragma unroll
            for (int e = 0; e < 4; e++) {
                int px = pxg * 8 + q * 4 + e;
                __nv_bfloat16 h0 = __float2bfloat16(v0[e]);
                __nv_bfloat16 h1 = __float2bfloat16(v1[e]);
                __nv_bfloat16 l0 = __float2bfloat16(v0[e] - __bfloat162float(h0));
                __nv_bfloat16 l1 = __float2bfloat16(v1[e] - __bfloat162float(h1));
                *(unsigned*)(xb + px * XCSTR) =
                    PKU(__bfloat16_as_ushort(h0), __bfloat16_as_ushort(h1));
                *(unsigned*)(xb + XCPART + px * XCSTR) =
                    PKU(__bfloat16_as_ushort(l0), __bfloat16_as_ushort(l1));
            }
        }
    }
    // W copy: 256 rows (hi/lo x 128 oc), 8x16B each
    {
        int part = t >> 7, oc = t & 127;
        const __nv_bfloat16* ws = (part ? wcl : wch) + oc * 64;
        const uint4* s = (const uint4*)ws;
        uint4* d = (uint4*)(smem + WCOFF + part * WCPART + oc * XCSTR);
        #pragma unroll
        for (int q = 0; q < 8; q++) d[q] = s[q];
    }
    __syncthreads();

    float acc[4][2][4];
    #pragma unroll
    for (int mt = 0; mt < 4; mt++)
        #pragma unroll
        for (int nt = 0; nt < 2; nt++)
            #pragma unroll
            for (int e = 0; e < 4; e++) acc[mt][nt][e] = 0.0f;

    #pragma unroll 1
    for (int pass = 0; pass < 3; pass++) {
        const char* A  = smem + WCOFF + ((pass == 1) ? WCPART : 0);
        const char* Bp = smem + ((pass == 2) ? XCPART : 0);
        #pragma unroll
        for (int k4 = 0; k4 < 4; k4++) {
            int kb = (k4 * 16 + 2 * tg) * 2;
            unsigned af[4][4];
            #pragma unroll
            for (int mt = 0; mt < 4; mt++) {
                const char* ar = A + (ocb + mt * 16 + g) * XCSTR + kb;
                af[mt][0] = *(const unsigned*)ar;
                af[mt][1] = *(const unsigned*)(ar + 8 * XCSTR);
                af[mt][2] = *(const unsigned*)(ar + 16);
                af[mt][3] = *(const unsigned*)(ar + 8 * XCSTR + 16);
            }
            #pragma unroll
            for (int nt = 0; nt < 2; nt++) {
                const char* br = Bp + (pxb + nt * 8 + g) * XCSTR + kb;
                unsigned b0 = *(const unsigned*)br;
                unsigned b1v = *(const unsigned*)(br + 16);
                #pragma unroll
                for (int mt = 0; mt < 4; mt++)
                    mma16816(acc[mt][nt], af[mt], b0, b1v);
            }
        }
    }

    float* dstb = out + (((size_t)(b * COUT)) << 16) + p0;
    #pragma unroll
    for (int mt = 0; mt < 4; mt++) {
        int oc_a = ocb + mt * 16 + g;
        int oc_b = oc_a + 8;
        float ba = bc[oc_a], bbv = bc[oc_b];
        float* da = dstb + (((size_t)oc_a) << 16) + pxb;
        float* db = dstb + (((size_t)oc_b) << 16) + pxb;
        float sa = 0.f, qa = 0.f, sb = 0.f, qb = 0.f;
        #pragma unroll
        for (int nt = 0; nt < 2; nt++) {
            int n0 = nt * 8 + tg * 2;
            float2 e0, e1;
            e0.x = fmaxf(acc[mt][nt][0] + ba, 0.f);
            e0.y = fmaxf(acc[mt][nt][1] + ba, 0.f);
            e1.x = fmaxf(acc[mt][nt][2] + bbv, 0.f);
            e1.y = fmaxf(acc[mt][nt][3] + bbv, 0.f);
            sa += e0.x + e0.y; qa += e0.x * e0.x + e0.y * e0.y;
            sb += e1.x + e1.y; qb += e1.x * e1.x + e1.y * e1.y;
            *(float2*)(da + n0) = e0;
            *(float2*)(db + n0) = e1;
        }
        quad_stats(sa, qa, tg, &d_sum0[oc_a], &d_sq0[oc_a]);
        quad_stats(sb, qb, tg, &d_sum0[oc_b], &d_sq0[oc_b]);
    }
}

__global__ __launch_bounds__(256) void bnapply_kernel(float* __restrict__ y) {
    int nth = gridDim.x * blockDim.x;
    int total = (B_ * COUT * HW) / 4;
    for (int i = blockIdx.x * blockDim.x + threadIdx.x; i < total; i += nth) {
        int c = (i >> 14) & 127;
        float4 v = reinterpret_cast<float4*>(y)[i];
        float a = d_a0[c], bb = d_b0[c];
        v.x = a * v.x + bb; v.y = a * v.y + bb;
        v.z = a * v.z + bb; v.w = a * v.w + bb;
        reinterpret_cast<float4*>(y)[i] = v;
    }
}

// ---------------- conv1: gather + 1x1 128->256 via fp16 HMMA 2-pass, cp.async W ----------------
#define X1STR  144
#define X1PART 9216
#define X1BLK  18432
#define W1OFF  36864
#define SMEM_C1M (W1OFF + 36864)
__global__ __launch_bounds__(256, 2) void conv1m_kernel(const float* __restrict__ xbn,
                                                        const int* __restrict__ abi,
                                                        const float* __restrict__ b1) {
    extern __shared__ float smf[];
    char* smem = (char*)smf;
    uint32_t sbase = (uint32_t)__cvta_generic_to_shared(smem);
    int t = threadIdx.x, w = t >> 5, lane = t & 31;
    int g = lane >> 2, tg = lane & 3;
    int blk0 = blockIdx.x * 2;
    int mblk = w >> 2;
    int ocb  = (w & 3) * 64;

    float acc[4][8][4];
    #pragma unroll
    for (int mt = 0; mt < 4; mt++)
        #pragma unroll
        for (int nt = 0; nt < 8; nt++)
            #pragma unroll
            for (int e = 0; e < 4; e++) acc[mt][nt][e] = 0.0f;

    int brow = t >> 1, bsub = t & 1;
    int xblk = brow >> 6, xic = brow & 63;
    int n_  = abi[(blk0 + xblk) * 3 + 0];
    int bi_ = abi[(blk0 + xblk) * 3 + 1];
    int bj_ = abi[(blk0 + xblk) * 3 + 2];
    const float* gsrc0 = xbn + (((size_t)(n_ * COUT)) << 16) + bi_ * 2048 + bj_ * 8;

    for (int chunk = 0; chunk < 2; chunk++) {
        __syncthreads();
        {
            #pragma unroll
            for (int j = 0; j < 8; j++) {
                int idx = t + j * 256;
                int row = idx >> 3, q = idx & 7;
                const __half* gs = w116 + (size_t)chunk * 16384 + row * 64 + q * 8;
                uint32_t sd = sbase + W1OFF + row * X1STR + q * 16;
                cp_async16(sd, gs);
            }
            CP_COMMIT();
        }
        {
            int icg = chunk * 64 + xic;
            const float* src = gsrc0 + (((size_t)icg) << 16) + bsub * 4 * 256;
            char* xb = smem + xblk * X1BLK + xic * 2;
            #pragma unroll
            for (int r4 = 0; r4 < 4; r4++) {
                float4 u  = *reinterpret_cast<const float4*>(src + r4 * 256);
                float4 v2 = *reinterpret_cast<const float4*>(src + r4 * 256 + 4);
                float vals[8] = {u.x, u.y, u.z, u.w, v2.x, v2.y, v2.z, v2.w};
                int px0 = bsub * 32 + r4 * 8;
                #pragma unroll
                for (int e = 0; e < 8; e++) {
                    float xv = vals[e];
                    __half h = __float2half(xv);
                    __half l = __float2half(xv - __half2float(h));
                    *(__half*)(xb + (px0 + e) * X1STR) = h;
                    *(__half*)(xb + X1PART + (px0 + e) * X1STR) = l;
                }
            }
        }
        CP_WAIT0();
        __syncthreads();

        const char* A  = smem + W1OFF;
        const char* Bh = smem + mblk * X1BLK;
        #pragma unroll
        for (int k4 = 0; k4 < 4; k4++) {
            int kb = (k4 * 16 + 2 * tg) * 2;
            unsigned af[4][4];
            #pragma unroll
            for (int mt = 0; mt < 4; mt++) {
                const char* ar = A + (ocb + mt * 16 + g) * X1STR + kb;
                af[mt][0] = *(const unsigned*)ar;
                af[mt][1] = *(const unsigned*)(ar + 8 * X1STR);
                af[mt][2] = *(const unsigned*)(ar + 16);
                af[mt][3] = *(const unsigned*)(ar + 8 * X1STR + 16);
            }
            #pragma unroll
            for (int nt = 0; nt < 8; nt++) {
                const char* br = Bh + (nt * 8 + g) * X1STR + kb;
                unsigned b0h = *(const unsigned*)br;
                unsigned b1h = *(const unsigned*)(br + 16);
                unsigned b0l = *(const unsigned*)(br + X1PART);
                unsigned b1l = *(const unsigned*)(br + X1PART + 16);
                #pragma unroll
                for (int mt = 0; mt < 4; mt++) {
                    mma16816h(acc[mt][nt], af[mt], b0h, b1h);
                    mma16816h(acc[mt][nt], af[mt], b0l, b1l);
                }
            }
        }
    }

    #pragma unroll
    for (int mt = 0; mt < 4; mt++) {
        int oc_a = ocb + mt * 16 + g;
        int oc_b = oc_a + 8;
        float ba = b1[oc_a], bbv = b1[oc_b];
        float* da = g1buf + ((size_t)(blk0 + mblk) * C2 + oc_a) * 64;
        float* db = g1buf + ((size_t)(blk0 + mblk) * C2 + oc_b) * 64;
        float sa = 0.f, qa = 0.f, sb = 0.f, qb = 0.f;
        #pragma unroll
        for (int nt = 0; nt < 8; nt++) {
            int n0 = nt * 8 + tg * 2;
            float2 e0, e1;
            e0.x = fmaxf(acc[mt][nt][0] + ba, 0.f);
            e0.y = fmaxf(acc[mt][nt][1] + ba, 0.f);
            e1.x = fmaxf(acc[mt][nt][2] + bbv, 0.f);
            e1.y = fmaxf(acc[mt][nt][3] + bbv, 0.f);
            sa += e0.x + e0.y; qa += e0.x * e0.x + e0.y * e0.y;
            sb += e1.x + e1.y; qb += e1.x * e1.x + e1.y * e1.y;
            *(float2*)(da + n0) = e0;
            *(float2*)(db + n0) = e1;
        }
        quad_stats(sa, qa, tg, &d_sum1[oc_a], &d_sq1[oc_a]);
        quad_stats(sb, qb, tg, &d_sum1[oc_b], &d_sq1[oc_b]);
    }
}

// ---------------- conv2: 3x3 via fp16 HMMA 2-pass, padded-2D X, cp.async dbuf W ----------------
#define X2ARR  14400
#define X2BLK  28800
#define W2OFF  57600
#define W2BUF  36864
#define SMEM_C2M (W2OFF + 2 * W2BUF)
__global__ __launch_bounds__(256, 1) void conv2m_kernel(const float* __restrict__ b2) {
    extern __shared__ float smf[];
    char* smem = (char*)smf;
    uint32_t sbase = (uint32_t)__cvta_generic_to_shared(smem);
    int t = threadIdx.x, w = t >> 5, lane = t & 31;
    int g = lane >> 2, tg = lane & 3;
    int blk0 = blockIdx.x * 2;
    int mblk = w >> 2;
    int ocb  = (w & 3) * 64;

    float acc[4][8][4];
    #pragma unroll
    for (int mt = 0; mt < 4; mt++)
        #pragma unroll
        for (int nt = 0; nt < 8; nt++)
            #pragma unroll
            for (int e = 0; e < 4; e++) acc[mt][nt][e] = 0.0f;

    for (int i = t; i < W2OFF / 16; i += 256) ((uint4*)smem)[i] = make_uint4(0, 0, 0, 0);

    int xblk = t >> 7;
    int icp  = (t >> 2) & 31;
    int pxg  = t & 3;

    for (int chunk = 0; chunk < 4; chunk++) {
        __syncthreads();
        {
            int tc = chunk;
            #pragma unroll
            for (int j = 0; j < 8; j++) {
                int idx = t + j * 256;
                int row = idx >> 3, q = idx & 7;
                const __half* gs = w216 + (size_t)tc * 16384 + row * 64 + q * 8;
                uint32_t sd = sbase + W2OFF + row * X1STR + q * 16;
                cp_async16(sd, gs);
            }
            CP_COMMIT();
        }
        {
            int ic0 = chunk * 64 + icp * 2;
            const float* s0 = g1buf + ((size_t)(blk0 + xblk) * C2 + ic0) * 64 + pxg * 16;
            const float* s1 = s0 + 64;
            float a0 = d_a1[ic0],     c0 = d_b1[ic0];
            float a1 = d_a1[ic0 + 1], c1 = d_b1[ic0 + 1];
            char* xb = smem + xblk * X2BLK + icp * 4;
            #pragma unroll
            for (int q = 0; q < 4; q++) {
                float4 u0 = ((const float4*)s0)[q];
                float4 u1 = ((const float4*)s1)[q];
                float v0[4] = {u0.x, u0.y, u0.z, u0.w};
                float v1[4] = {u1.x, u1.y, u1.z, u1.w};
                #pragma unroll
                for (int e = 0; e < 4; e++) {
                    int p = pxg * 16 + q * 4 + e;
                    int row = ((p >> 3) + 1) * 10 + (p & 7) + 1;
                    float x0 = a0 * v0[e] + c0;
                    float x1 = a1 * v1[e] + c1;
                    __half h0 = __float2half(x0);
                    __half h1 = __float2half(x1);
                    __half l0 = __float2half(x0 - __half2float(h0));
                    __half l1 = __float2half(x1 - __half2float(h1));
                    *(unsigned*)(xb + row * X1STR) =
                        PKU(__half_as_ushort(h0), __half_as_ushort(h1));
                    *(unsigned*)(xb + X2ARR + row * X1STR) =
                        PKU(__half_as_ushort(l0), __half_as_ushort(l1));
                }
            }
        }

        for (int tap = 0; tap < 9; tap++) {
            CP_WAIT0();
            __syncthreads();
            int buf = tap & 1;
            if (tap < 8) {
                int tc = (tap + 1) * 4 + chunk;
                int ob = buf ^ 1;
                #pragma unroll
                for (int j = 0; j < 8; j++) {
                    int idx = t + j * 256;
                    int row = idx >> 3, q = idx & 7;
                    const __half* gs = w216 + (size_t)tc * 16384 + row * 64 + q * 8;
                    uint32_t sd = sbase + W2OFF + ob * W2BUF + row * X1STR + q * 16;
                    cp_async16(sd, gs);
                }
                CP_COMMIT();
            }

            int dr = tap / 3, dc = tap % 3;
            int rowc = dr * 10 + dc + g;
            const char* A  = smem + W2OFF + buf * W2BUF;
            const char* Bh = smem + mblk * X2BLK;
            #pragma unroll
            for (int k4 = 0; k4 < 4; k4++) {
                int kb = (k4 * 16 + 2 * tg) * 2;
                unsigned af[4][4];
                #pragma unroll
                for (int mt = 0; mt < 4; mt++) {
                    const char* ar = A + (ocb + mt * 16 + g) * X1STR + kb;
                    af[mt][0] = *(const unsigned*)ar;
                    af[mt][1] = *(const unsigned*)(ar + 8 * X1STR);
                    af[mt][2] = *(const unsigned*)(ar + 16);
                    af[mt][3] = *(const unsigned*)(ar + 8 * X1STR + 16);
                }
                #pragma unroll
                for (int nt = 0; nt < 8; nt++) {
                    const char* br = Bh + (rowc + nt * 10) * X1STR + kb;
                    unsigned b0h = *(const unsigned*)br;
                    unsigned b1h = *(const unsigned*)(br + 16);
                    unsigned b0l = *(const unsigned*)(br + X2ARR);
                    unsigned b1l = *(const unsigned*)(br + X2ARR + 16);
                    #pragma unroll
                    for (int mt = 0; mt < 4; mt++) {
                        mma16816h(acc[mt][nt], af[mt], b0h, b1h);
                        mma16816h(acc[mt][nt], af[mt], b0l, b1l);
                    }
                }
            }
        }
    }

    #pragma unroll
    for (int mt = 0; mt < 4; mt++) {
        int oc_a = ocb + mt * 16 + g;
        int oc_b = oc_a + 8;
        float ba = b2[oc_a], bbv = b2[oc_b];
        float* da = g2buf + ((size_t)(blk0 + mblk) * C2 + oc_a) * 64;
        float* db = g2buf + ((size_t)(blk0 + mblk) * C2 + oc_b) * 64;
        float sa = 0.f, qa = 0.f, sb = 0.f, qb = 0.f;
        #pragma unroll
        for (int nt = 0; nt < 8; nt++) {
            int n0 = nt * 8 + tg * 2;
            float2 e0, e1;
            e0.x = fmaxf(acc[mt][nt][0] + ba, 0.f);
            e0.y = fmaxf(acc[mt][nt][1] + ba, 0.f);
            e1.x = fmaxf(acc[mt][nt][2] + bbv, 0.f);
            e1.y = fmaxf(acc[mt][nt][3] + bbv, 0.f);
            sa += e0.x + e0.y; qa += e0.x * e0.x + e0.y * e0.y;
            sb += e1.x + e1.y; qb += e1.x * e1.x + e1.y * e1.y;
            *(float2*)(da + n0) = e0;
            *(float2*)(db + n0) = e1;
        }
        quad_stats(sa, qa, tg, &d_sum2[oc_a], &d_sq2[oc_a]);
        quad_stats(sb, qb, tg, &d_sum2[oc_b], &d_sq2[oc_b]);
    }
}

// ---------------- conv3: 1x1 256->128 via fp16 HMMA 2-pass, 4 blocks/CTA, cp.async W ----------------
#define X3BLK  18432
#define W3OFF  73728
#define SMEM_C3M (W3OFF + 18432)
__global__ __launch_bounds__(256, 2) void conv3m_kernel(const float* __restrict__ b3) {
    extern __shared__ float smf[];
    char* smem = (char*)smf;
    uint32_t sbase = (uint32_t)__cvta_generic_to_shared(smem);
    int t = threadIdx.x, w = t >> 5, lane = t & 31;
    int g = lane >> 2, tg = lane & 3;
    int blk0 = blockIdx.x * 4;
    int mblk = w >> 1;
    int ocb  = (w & 1) * 64;

    float acc[4][8][4];
    #pragma unroll
    for (int mt = 0; mt < 4; mt++)
        #pragma unroll
        for (int nt = 0; nt < 8; nt++)
            #pragma unroll
            for (int e = 0; e < 4; e++) acc[mt][nt][e] = 0.0f;

    int xblk = t >> 6, xic = t & 63;

    for (int chunk = 0; chunk < 4; chunk++) {
        __syncthreads();
        {
            #pragma unroll
            for (int j = 0; j < 4; j++) {
                int idx = t + j * 256;
                int row = idx >> 3, q = idx & 7;
                const __half* gs = w316 + (size_t)chunk * 8192 + row * 64 + q * 8;
                uint32_t sd = sbase + W3OFF + row * X1STR + q * 16;
                cp_async16(sd, gs);
            }
            CP_COMMIT();
        }
        {
            int icg = chunk * 64 + xic;
            const float* src = g2buf + ((size_t)(blk0 + xblk) * C2 + icg) * 64;
            float a = d_a2[icg], bb = d_b2[icg];
            char* xb = smem + xblk * X3BLK + xic * 2;
            #pragma unroll
            for (int j = 0; j < 16; j++) {
                float4 v4 = ((const float4*)src)[j];
                float vals[4] = {v4.x, v4.y, v4.z, v4.w};
                #pragma unroll
                for (int e = 0; e < 4; e++) {
                    int px = j * 4 + e;
                    float xv = a * vals[e] + bb;
                    __half h = __float2half(xv);
                    __half l = __float2half(xv - __half2float(h));
                    *(__half*)(xb + px * X1STR) = h;
                    *(__half*)(xb + X1PART + px * X1STR) = l;
                }
            }
        }
        CP_WAIT0();
        __syncthreads();

        const char* A  = smem + W3OFF;
        const char* Bh = smem + mblk * X3BLK;
        #pragma unroll
        for (int k4 = 0; k4 < 4; k4++) {
            int kb = (k4 * 16 + 2 * tg) * 2;
            unsigned af[4][4];
            #pragma unroll
            for (int mt = 0; mt < 4; mt++) {
                const char* ar = A + (ocb + mt * 16 + g) * X1STR + kb;
                af[mt][0] = *(const unsigned*)ar;
                af[mt][1] = *(const unsigned*)(ar + 8 * X1STR);
                af[mt][2] = *(const unsigned*)(ar + 16);
                af[mt][3] = *(const unsigned*)(ar + 8 * X1STR + 16);
            }
            #pragma unroll
            for (int nt = 0; nt < 8; nt++) {
                const char* br = Bh + (nt * 8 + g) * X1STR + kb;
                unsigned b0h = *(const unsigned*)br;
                unsigned b1h = *(const unsigned*)(br + 16);
                unsigned b0l = *(const unsigned*)(br + X1PART);
                unsigned b1l = *(const unsigned*)(br + X1PART + 16);
                #pragma unroll
                for (int mt = 0; mt < 4; mt++) {
                    mma16816h(acc[mt][nt], af[mt], b0h, b1h);
                    mma16816h(acc[mt][nt], af[mt], b0l, b1l);
                }
            }
        }
    }

    #pragma unroll
    for (int mt = 0; mt < 4; mt++) {
        int oc_a = ocb + mt * 16 + g;
        int oc_b = oc_a + 8;
        float ba = b3[oc_a], bbv = b3[oc_b];
        float* da = g3buf + ((size_t)(blk0 + mblk) * COUT + oc_a) * 64;
        float* db = g3buf + ((size_t)(blk0 + mblk) * COUT + oc_b) * 64;
        float sa = 0.f, qa = 0.f, sb = 0.f, qb = 0.f;
        #pragma unroll
        for (int nt = 0; nt < 8; nt++) {
            int n0 = nt * 8 + tg * 2;
            float2 e0, e1;
            e0.x = fmaxf(acc[mt][nt][0] + ba, 0.f);
            e0.y = fmaxf(acc[mt][nt][1] + ba, 0.f);
            e1.x = fmaxf(acc[mt][nt][2] + bbv, 0.f);
            e1.y = fmaxf(acc[mt][nt][3] + bbv, 0.f);
            sa += e0.x + e0.y; qa += e0.x * e0.x + e0.y * e0.y;
            sb += e1.x + e1.y; qb += e1.x * e1.x + e1.y * e1.y;
            *(float2*)(da + n0) = e0;
            *(float2*)(db + n0) = e1;
        }
        quad_stats(sa, qa, tg, &d_sum3[oc_a], &d_sq3[oc_a]);
        quad_stats(sb, qb, tg, &d_sum3[oc_b], &d_sq3[oc_b]);
    }
}

// ---------------- scatter: BN3(g3) -> image ----------------
__global__ __launch_bounds__(256) void scatter_kernel(const int* __restrict__ abi,
                                                      float* __restrict__ out) {
    int blk = blockIdx.x;
    int n  = abi[blk * 3 + 0];
    int bi = abi[blk * 3 + 1];
    int bj = abi[blk * 3 + 2];
    const float* src = g3buf + (size_t)blk * COUT * 64;
    float* dst = out + (((size_t)(n * COUT)) << 16) + bi * 8 * 256 + bj * 8;
    for (int i = threadIdx.x; i < 2048; i += 256) {
        int c = i >> 4, q = i & 15;
        int r = q >> 1, c4 = (q & 1) * 4;
        float4 v = *reinterpret_cast<const float4*>(src + c * 64 + q * 4);
        float a = d_a3[c], bb = d_b3[c];
        v.x = a * v.x + bb; v.y = a * v.y + bb;
        v.z = a * v.z + bb; v.w = a * v.w + bb;
        *reinterpret_cast<float4*>(dst + (((size_t)c) << 16) + r * 256 + c4) = v;
    }
}

// ---------------- launch ----------------
extern "C" void kernel_launch(void* const* d_in, const int* in_sizes, int n_in,
                              void* d_out, int out_size) {
    const float* x    = (const float*)d_in[0];
    const int*   abi  = (const int*)  d_in[1];
    const float* w_c  = (const float*)d_in[2];
    const float* b_c  = (const float*)d_in[3];
    const float* gm_c = (const float*)d_in[4];
    const float* be_c = (const float*)d_in[5];
    const float* w1   = (const float*)d_in[6];
    const float* b1   = (const float*)d_in[7];
    const float* gm1  = (const float*)d_in[8];
    const float* be1  = (const float*)d_in[9];
    const float* w2   = (const float*)d_in[10];
    const float* b2   = (const float*)d_in[11];
    const float* gm2  = (const float*)d_in[12];
    const float* be2  = (const float*)d_in[13];
    const float* w3   = (const float*)d_in[14];
    const float* b3   = (const float*)d_in[15];
    const float* gm3  = (const float*)d_in[16];
    const float* be3  = (const float*)d_in[17];
    float* out = (float*)d_out;

    cudaFuncSetAttribute(convcm_kernel, cudaFuncAttributeMaxDynamicSharedMemorySize, SMEM_CCM);
    cudaFuncSetAttribute(conv1m_kernel, cudaFuncAttributeMaxDynamicSharedMemorySize, SMEM_C1M);
    cudaFuncSetAttribute(conv2m_kernel, cudaFuncAttributeMaxDynamicSharedMemorySize, SMEM_C2M);
    cudaFuncSetAttribute(conv3m_kernel, cudaFuncAttributeMaxDynamicSharedMemorySize, SMEM_C3M);

    zero_stats_kernel<<<1, 256>>>();
    w2cvt_kernel<<<576, 256>>>(w2);
    w13cvt_kernel<<<64, 256>>>(w1, w3, w_c);

    convcm_kernel<<<8192, 256, SMEM_CCM>>>(x, b_c, out);
    finalize_kernel<<<1, 256>>>(0, gm_c, be_c, 1.0 / 524288.0);
    bnapply_kernel<<<16384, 256>>>(out);

    conv1m_kernel<<<2048, 256, SMEM_C1M>>>(out, abi, b1);
    finalize_kernel<<<1, 256>>>(1, gm1, be1, 1.0 / 262144.0);

    conv2m_kernel<<<2048, 256, SMEM_C2M>>>(b2);
    finalize_kernel<<<1, 256>>>(2, gm2, be2, 1.0 / 262144.0);

    conv3m_kernel<<<1024, 256, SMEM_C3M>>>(b3);
    finalize_kernel<<<1, 256>>>(3, gm3, be3, 1.0 / 262144.0);

    scatter_kernel<<<4096, 256>>>(abi, out);
}

// round 14
// speedup vs baseline: 1.1671x; 1.1671x over previous
#include <cuda_runtime.h>
#include <cuda_bf16.h>
#include <cuda_fp16.h>
#include <math.h>
#include <stdint.h>

#define B_    8
#define CIN   64
#define COUT  128
#define C2    256
#define HW    65536
#define NBLK  4096
#define EPSV  1e-5f

// ---------------- scratch ----------------
__device__ float g1buf[(size_t)NBLK * C2 * 64];
__device__ float g2buf[(size_t)NBLK * C2 * 64];
__device__ float g3buf[(size_t)NBLK * COUT * 64];

// fp16 weights (block convs), bf16 hi/lo for convc
__device__ __half w216[36 * 16384];  // [tap*4+chunk][oc 256][ic 64]
__device__ __half w116[2 * 16384];   // [chunk2][oc 256][ic 64]
__device__ __half w316[4 * 8192];    // [chunk4][oc 128][ic 64]
__device__ __nv_bfloat16 wch[8192];  // [oc 128][ic 64]
__device__ __nv_bfloat16 wcl[8192];

__device__ double d_sum0[COUT], d_sq0[COUT];
__device__ double d_sum1[C2],   d_sq1[C2];
__device__ double d_sum2[C2],   d_sq2[C2];
__device__ double d_sum3[COUT], d_sq3[COUT];
__device__ float  d_a0[COUT], d_b0[COUT];
__device__ float  d_a1[C2],   d_b1[C2];
__device__ float  d_a2[C2],   d_b2[C2];
__device__ float  d_a3[COUT], d_b3[COUT];

#define PKU(x, y) ((unsigned)(x) | ((unsigned)(y) << 16))

// ---------------- MMA helpers ----------------
__device__ __forceinline__ void mma16816(float* d, const unsigned* a, unsigned b0, unsigned b1) {
    asm volatile(
        "mma.sync.aligned.m16n8k16.row.col.f32.bf16.bf16.f32 "
        "{%0,%1,%2,%3}, {%4,%5,%6,%7}, {%8,%9}, {%0,%1,%2,%3};"
        : "+f"(d[0]), "+f"(d[1]), "+f"(d[2]), "+f"(d[3])
        : "r"(a[0]), "r"(a[1]), "r"(a[2]), "r"(a[3]), "r"(b0), "r"(b1));
}
__device__ __forceinline__ void mma16816h(float* d, const unsigned* a, unsigned b0, unsigned b1) {
    asm volatile(
        "mma.sync.aligned.m16n8k16.row.col.f32.f16.f16.f32 "
        "{%0,%1,%2,%3}, {%4,%5,%6,%7}, {%8,%9}, {%0,%1,%2,%3};"
        : "+f"(d[0]), "+f"(d[1]), "+f"(d[2]), "+f"(d[3])
        : "r"(a[0]), "r"(a[1]), "r"(a[2]), "r"(a[3]), "r"(b0), "r"(b1));
}

__device__ __forceinline__ void cp_async16(uint32_t sdst, const void* gsrc) {
    asm volatile("cp.async.cg.shared.global [%0], [%1], 16;" :: "r"(sdst), "l"(gsrc));
}
#define CP_COMMIT() asm volatile("cp.async.commit_group;" ::: "memory")
#define CP_WAIT0()  asm volatile("cp.async.wait_group 0;" ::: "memory")

__device__ __forceinline__ void quad_stats(float s, float s2, int tg,
                                           double* gsum, double* gsq) {
    s  += __shfl_xor_sync(0xffffffffu, s, 1);
    s  += __shfl_xor_sync(0xffffffffu, s, 2);
    s2 += __shfl_xor_sync(0xffffffffu, s2, 1);
    s2 += __shfl_xor_sync(0xffffffffu, s2, 2);
    if (tg == 0) { atomicAdd(gsum, (double)s); atomicAdd(gsq, (double)s2); }
}

// ---------------- utility ----------------
__global__ void zero_stats_kernel() {
    int t = threadIdx.x;
    if (t < COUT) { d_sum0[t] = 0.0; d_sq0[t] = 0.0; d_sum3[t] = 0.0; d_sq3[t] = 0.0; }
    d_sum1[t] = 0.0; d_sq1[t] = 0.0; d_sum2[t] = 0.0; d_sq2[t] = 0.0;
}

__global__ void finalize_kernel(int stage, const float* __restrict__ gamma,
                                const float* __restrict__ beta, double invN) {
    int t = threadIdx.x;
    const double *sum, *sq; float *a, *bsh; int C;
    if (stage == 0)      { sum = d_sum0; sq = d_sq0; a = d_a0; bsh = d_b0; C = COUT; }
    else if (stage == 1) { sum = d_sum1; sq = d_sq1; a = d_a1; bsh = d_b1; C = C2; }
    else if (stage == 2) { sum = d_sum2; sq = d_sq2; a = d_a2; bsh = d_b2; C = C2; }
    else                 { sum = d_sum3; sq = d_sq3; a = d_a3; bsh = d_b3; C = COUT; }
    if (t < C) {
        double mean = sum[t] * invN;
        double var  = sq[t] * invN - mean * mean;
        float v = fmaxf((float)var, 0.0f);
        float av = gamma[t] * rsqrtf(v + EPSV);
        a[t] = av;
        bsh[t] = beta[t] - av * (float)mean;
    }
}

// ---------------- weight converts ----------------
__global__ __launch_bounds__(256) void w2cvt_kernel(const float* __restrict__ w2) {
    int i4 = blockIdx.x * 256 + threadIdx.x;
    int ic0 = (i4 & 15) * 4;
    int oc  = (i4 >> 4) & 255;
    int tc  = i4 >> 12;
    int tap = tc >> 2, chunk = tc & 3;
    #pragma unroll
    for (int e = 0; e < 4; e++) {
        int ic = ic0 + e;
        float v = w2[(size_t)oc * 2304 + (chunk * 64 + ic) * 9 + tap];
        w216[(size_t)tc * 16384 + oc * 64 + ic] = __float2half(v);
    }
}

__global__ __launch_bounds__(256) void w13cvt_kernel(const float* __restrict__ w1,
                                                     const float* __restrict__ w3,
                                                     const float* __restrict__ wc) {
    int i = blockIdx.x * 256 + threadIdx.x;   // 0..16383
    {
        #pragma unroll
        for (int e = 0; e < 2; e++) {
            int idx = i * 2 + e;
            int ic = idx & 63, oc = (idx >> 6) & 255, ch = idx >> 14;
            w116[idx] = __float2half(w1[(size_t)oc * 128 + ch * 64 + ic]);
        }
    }
    {
        #pragma unroll
        for (int e = 0; e < 2; e++) {
            int idx = i * 2 + e;
            int ic = idx & 63, oc = (idx >> 6) & 127, ch = idx >> 13;
            w316[idx] = __float2half(w3[(size_t)oc * 256 + ch * 64 + ic]);
        }
    }
    if (i < 8192) {
        float v = wc[i];
        __nv_bfloat16 h = __float2bfloat16(v);
        wch[i] = h;
        wcl[i] = __float2bfloat16(v - __bfloat162float(h));
    }
}

// ---------------- convc: 1x1 64->128 via bf16 HMMA 3-pass, 128 px/CTA, fused stats ----------------
#define XCSTR  144
#define XCPART 18432
#define WCOFF  36864
#define WCPART 18432
#define SMEM_CCM (WCOFF + 2 * WCPART)
__global__ __launch_bounds__(256, 2) void convcm_kernel(const float* __restrict__ x,
                                                        const float* __restrict__ bc,
                                                        float* __restrict__ out) {
    extern __shared__ float smf[];
    char* smem = (char*)smf;
    int t = threadIdx.x, w = t >> 5, lane = t & 31;
    int g = lane >> 2, tg = lane & 3;
    int b  = blockIdx.x >> 9;
    int p0 = (blockIdx.x & 511) << 7;
    int ocb = (w & 1) * 64;
    int pxb = (w >> 1) * 32;

    {
        int icp = t & 31, pxg = t >> 5;
        const float* s0 = x + (((size_t)(b * CIN + icp * 2)) << 16) + p0 + pxg * 16;
        const float* s1 = s0 + HW;
        char* xb = smem + icp * 4;
        #pragma unroll
        for (int q = 0; q < 4; q++) {
            float4 u0 = ((const float4*)s0)[q];
            float4 u1 = ((const float4*)s1)[q];
            float v0[4] = {u0.x, u0.y, u0.z, u0.w};
            float v1[4] = {u1.x, u1.y, u1.z, u1.w};
            #pragma unroll
            for (int e = 0; e < 4; e++) {
                int px = pxg * 16 + q * 4 + e;
                __nv_bfloat16 h0 = __float2bfloat16(v0[e]);
                __nv_bfloat16 h1 = __float2bfloat16(v1[e]);
                __nv_bfloat16 l0 = __float2bfloat16(v0[e] - __bfloat162float(h0));
                __nv_bfloat16 l1 = __float2bfloat16(v1[e] - __bfloat162float(h1));
                *(unsigned*)(xb + px * XCSTR) =
                    PKU(__bfloat16_as_ushort(h0), __bfloat16_as_ushort(h1));
                *(unsigned*)(xb + XCPART + px * XCSTR) =
                    PKU(__bfloat16_as_ushort(l0), __bfloat16_as_ushort(l1));
            }
        }
    }
    {
        int part = t >> 7, oc = t & 127;
        const __nv_bfloat16* ws = (part ? wcl : wch) + oc * 64;
        const uint4* s = (const uint4*)ws;
        uint4* d = (uint4*)(smem + WCOFF + part * WCPART + oc * XCSTR);
        #pragma unroll
        for (int q = 0; q < 8; q++) d[q] = s[q];
    }
    __syncthreads();

    float acc[4][4][4];
    #pragma unroll
    for (int mt = 0; mt < 4; mt++)
        #pragma unroll
        for (int nt = 0; nt < 4; nt++)
            #pragma unroll
            for (int e = 0; e < 4; e++) acc[mt][nt][e] = 0.0f;

    #pragma unroll 1
    for (int pass = 0; pass < 3; pass++) {
        const char* A  = smem + WCOFF + ((pass == 1) ? WCPART : 0);
        const char* Bp = smem + ((pass == 2) ? XCPART : 0);
        #pragma unroll
        for (int k4 = 0; k4 < 4; k4++) {
            int kb = (k4 * 16 + 2 * tg) * 2;
            unsigned af[4][4];
            #pragma unroll
            for (int mt = 0; mt < 4; mt++) {
                const char* ar = A + (ocb + mt * 16 + g) * XCSTR + kb;
                af[mt][0] = *(const unsigned*)ar;
                af[mt][1] = *(const unsigned*)(ar + 8 * XCSTR);
                af[mt][2] = *(const unsigned*)(ar + 16);
                af[mt][3] = *(const unsigned*)(ar + 8 * XCSTR + 16);
            }
            #pragma unroll
            for (int nt = 0; nt < 4; nt++) {
                const char* br = Bp + (pxb + nt * 8 + g) * XCSTR + kb;
                unsigned b0 = *(const unsigned*)br;
                unsigned b1v = *(const unsigned*)(br + 16);
                #pragma unroll
                for (int mt = 0; mt < 4; mt++)
                    mma16816(acc[mt][nt], af[mt], b0, b1v);
            }
        }
    }

    float* dstb = out + (((size_t)(b * COUT)) << 16) + p0;
    #pragma unroll
    for (int mt = 0; mt < 4; mt++) {
        int oc_a = ocb + mt * 16 + g;
        int oc_b = oc_a + 8;
        float ba = bc[oc_a], bbv = bc[oc_b];
        float* da = dstb + (((size_t)oc_a) << 16) + pxb;
        float* db = dstb + (((size_t)oc_b) << 16) + pxb;
        float sa = 0.f, qa = 0.f, sb = 0.f, qb = 0.f;
        #pragma unroll
        for (int nt = 0; nt < 4; nt++) {
            int n0 = nt * 8 + tg * 2;
            float2 e0, e1;
            e0.x = fmaxf(acc[mt][nt][0] + ba, 0.f);
            e0.y = fmaxf(acc[mt][nt][1] + ba, 0.f);
            e1.x = fmaxf(acc[mt][nt][2] + bbv, 0.f);
            e1.y = fmaxf(acc[mt][nt][3] + bbv, 0.f);
            sa += e0.x + e0.y; qa += e0.x * e0.x + e0.y * e0.y;
            sb += e1.x + e1.y; qb += e1.x * e1.x + e1.y * e1.y;
            *(float2*)(da + n0) = e0;
            *(float2*)(db + n0) = e1;
        }
        quad_stats(sa, qa, tg, &d_sum0[oc_a], &d_sq0[oc_a]);
        quad_stats(sb, qb, tg, &d_sum0[oc_b], &d_sq0[oc_b]);
    }
}

__global__ __launch_bounds__(256) void bnapply_kernel(float* __restrict__ y) {
    int nth = gridDim.x * blockDim.x;
    int total = (B_ * COUT * HW) / 4;
    for (int i = blockIdx.x * blockDim.x + threadIdx.x; i < total; i += nth) {
        int c = (i >> 14) & 127;
        float4 v = reinterpret_cast<float4*>(y)[i];
        float a = d_a0[c], bb = d_b0[c];
        v.x = a * v.x + bb; v.y = a * v.y + bb;
        v.z = a * v.z + bb; v.w = a * v.w + bb;
        reinterpret_cast<float4*>(y)[i] = v;
    }
}

// ---------------- conv1: gather + 1x1 128->256 via fp16 HMMA 2-pass, cp.async W ----------------
#define X1STR  144
#define X1PART 9216
#define X1BLK  18432
#define W1OFF  36864
#define SMEM_C1M (W1OFF + 36864)
__global__ __launch_bounds__(256, 1) void conv1m_kernel(const float* __restrict__ xbn,
                                                        const int* __restrict__ abi,
                                                        const float* __restrict__ b1) {
    extern __shared__ float smf[];
    char* smem = (char*)smf;
    uint32_t sbase = (uint32_t)__cvta_generic_to_shared(smem);
    int t = threadIdx.x, w = t >> 5, lane = t & 31;
    int g = lane >> 2, tg = lane & 3;
    int blk0 = blockIdx.x * 2;
    int mblk = w >> 2;
    int ocb  = (w & 3) * 64;

    float acc[4][8][4];
    #pragma unroll
    for (int mt = 0; mt < 4; mt++)
        #pragma unroll
        for (int nt = 0; nt < 8; nt++)
            #pragma unroll
            for (int e = 0; e < 4; e++) acc[mt][nt][e] = 0.0f;

    int brow = t >> 1, bsub = t & 1;
    int xblk = brow >> 6, xic = brow & 63;
    int n_  = abi[(blk0 + xblk) * 3 + 0];
    int bi_ = abi[(blk0 + xblk) * 3 + 1];
    int bj_ = abi[(blk0 + xblk) * 3 + 2];
    const float* gsrc0 = xbn + (((size_t)(n_ * COUT)) << 16) + bi_ * 2048 + bj_ * 8;

    for (int chunk = 0; chunk < 2; chunk++) {
        __syncthreads();
        {
            #pragma unroll
            for (int j = 0; j < 8; j++) {
                int idx = t + j * 256;
                int row = idx >> 3, q = idx & 7;
                const __half* gs = w116 + (size_t)chunk * 16384 + row * 64 + q * 8;
                uint32_t sd = sbase + W1OFF + row * X1STR + q * 16;
                cp_async16(sd, gs);
            }
            CP_COMMIT();
        }
        {
            int icg = chunk * 64 + xic;
            const float* src = gsrc0 + (((size_t)icg) << 16) + bsub * 4 * 256;
            char* xb = smem + xblk * X1BLK + xic * 2;
            #pragma unroll
            for (int r4 = 0; r4 < 4; r4++) {
                float4 u  = *reinterpret_cast<const float4*>(src + r4 * 256);
                float4 v2 = *reinterpret_cast<const float4*>(src + r4 * 256 + 4);
                float vals[8] = {u.x, u.y, u.z, u.w, v2.x, v2.y, v2.z, v2.w};
                int px0 = bsub * 32 + r4 * 8;
                #pragma unroll
                for (int e = 0; e < 8; e++) {
                    float xv = vals[e];
                    __half h = __float2half(xv);
                    __half l = __float2half(xv - __half2float(h));
                    *(__half*)(xb + (px0 + e) * X1STR) = h;
                    *(__half*)(xb + X1PART + (px0 + e) * X1STR) = l;
                }
            }
        }
        CP_WAIT0();
        __syncthreads();

        const char* A  = smem + W1OFF;
        const char* Bh = smem + mblk * X1BLK;
        #pragma unroll
        for (int k4 = 0; k4 < 4; k4++) {
            int kb = (k4 * 16 + 2 * tg) * 2;
            unsigned af[4][4];
            #pragma unroll
            for (int mt = 0; mt < 4; mt++) {
                const char* ar = A + (ocb + mt * 16 + g) * X1STR + kb;
                af[mt][0] = *(const unsigned*)ar;
                af[mt][1] = *(const unsigned*)(ar + 8 * X1STR);
                af[mt][2] = *(const unsigned*)(ar + 16);
                af[mt][3] = *(const unsigned*)(ar + 8 * X1STR + 16);
            }
            #pragma unroll
            for (int nt = 0; nt < 8; nt++) {
                const char* br = Bh + (nt * 8 + g) * X1STR + kb;
                unsigned b0h = *(const unsigned*)br;
                unsigned b1h = *(const unsigned*)(br + 16);
                unsigned b0l = *(const unsigned*)(br + X1PART);
                unsigned b1l = *(const unsigned*)(br + X1PART + 16);
                #pragma unroll
                for (int mt = 0; mt < 4; mt++) {
                    mma16816h(acc[mt][nt], af[mt], b0h, b1h);
                    mma16816h(acc[mt][nt], af[mt], b0l, b1l);
                }
            }
        }
    }

    #pragma unroll
    for (int mt = 0; mt < 4; mt++) {
        int oc_a = ocb + mt * 16 + g;
        int oc_b = oc_a + 8;
        float ba = b1[oc_a], bbv = b1[oc_b];
        float* da = g1buf + ((size_t)(blk0 + mblk) * C2 + oc_a) * 64;
        float* db = g1buf + ((size_t)(blk0 + mblk) * C2 + oc_b) * 64;
        float sa = 0.f, qa = 0.f, sb = 0.f, qb = 0.f;
        #pragma unroll
        for (int nt = 0; nt < 8; nt++) {
            int n0 = nt * 8 + tg * 2;
            float2 e0, e1;
            e0.x = fmaxf(acc[mt][nt][0] + ba, 0.f);
            e0.y = fmaxf(acc[mt][nt][1] + ba, 0.f);
            e1.x = fmaxf(acc[mt][nt][2] + bbv, 0.f);
            e1.y = fmaxf(acc[mt][nt][3] + bbv, 0.f);
            sa += e0.x + e0.y; qa += e0.x * e0.x + e0.y * e0.y;
            sb += e1.x + e1.y; qb += e1.x * e1.x + e1.y * e1.y;
            *(float2*)(da + n0) = e0;
            *(float2*)(db + n0) = e1;
        }
        quad_stats(sa, qa, tg, &d_sum1[oc_a], &d_sq1[oc_a]);
        quad_stats(sb, qb, tg, &d_sum1[oc_b], &d_sq1[oc_b]);
    }
}

// ---------------- conv2: 3x3 via fp16 HMMA 2-pass, 1 block/CTA, 2 CTAs/SM ----------------
#define X2ARR  14400
#define X2BLK  28800
#define W2OFF  28800
#define W2BUF  36864
#define SMEM_C2M (W2OFF + 2 * W2BUF)
__global__ __launch_bounds__(256, 2) void conv2m_kernel(const float* __restrict__ b2) {
    extern __shared__ float smf[];
    char* smem = (char*)smf;
    uint32_t sbase = (uint32_t)__cvta_generic_to_shared(smem);
    int t = threadIdx.x, w = t >> 5, lane = t & 31;
    int g = lane >> 2, tg = lane & 3;
    int blk = blockIdx.x;
    int ocb = w * 32;

    float acc[2][8][4];
    #pragma unroll
    for (int mt = 0; mt < 2; mt++)
        #pragma unroll
        for (int nt = 0; nt < 8; nt++)
            #pragma unroll
            for (int e = 0; e < 4; e++) acc[mt][nt][e] = 0.0f;

    // zero X once (halo stays zero)
    for (int i = t; i < W2OFF / 16; i += 256) ((uint4*)smem)[i] = make_uint4(0, 0, 0, 0);

    int icp = t >> 3;       // 32 ic-pairs
    int pxg = t & 7;        // 8 px-groups of 8

    for (int chunk = 0; chunk < 4; chunk++) {
        __syncthreads();
        {
            int tc = chunk;
            #pragma unroll
            for (int j = 0; j < 8; j++) {
                int idx = t + j * 256;
                int row = idx >> 3, q = idx & 7;
                const __half* gs = w216 + (size_t)tc * 16384 + row * 64 + q * 8;
                uint32_t sd = sbase + W2OFF + row * X1STR + q * 16;
                cp_async16(sd, gs);
            }
            CP_COMMIT();
        }
        // X build: thread = (icp, pxg) handles 2 ic x 8 px
        {
            int ic0 = chunk * 64 + icp * 2;
            const float* s0 = g1buf + ((size_t)blk * C2 + ic0) * 64 + pxg * 8;
            const float* s1 = s0 + 64;
            float a0 = d_a1[ic0],     c0 = d_b1[ic0];
            float a1 = d_a1[ic0 + 1], c1 = d_b1[ic0 + 1];
            char* xb = smem + icp * 4;
            #pragma unroll
            for (int q = 0; q < 2; q++) {
                float4 u0 = ((const float4*)s0)[q];
                float4 u1 = ((const float4*)s1)[q];
                float v0[4] = {u0.x, u0.y, u0.z, u0.w};
                float v1[4] = {u1.x, u1.y, u1.z, u1.w};
                #pragma unroll
                for (int e = 0; e < 4; e++) {
                    int p = pxg * 8 + q * 4 + e;
                    int row = ((p >> 3) + 1) * 10 + (p & 7) + 1;
                    float x0 = a0 * v0[e] + c0;
                    float x1 = a1 * v1[e] + c1;
                    __half h0 = __float2half(x0);
                    __half h1 = __float2half(x1);
                    __half l0 = __float2half(x0 - __half2float(h0));
                    __half l1 = __float2half(x1 - __half2float(h1));
                    *(unsigned*)(xb + row * X1STR) =
                        PKU(__half_as_ushort(h0), __half_as_ushort(h1));
                    *(unsigned*)(xb + X2ARR + row * X1STR) =
                        PKU(__half_as_ushort(l0), __half_as_ushort(l1));
                }
            }
        }

        for (int tap = 0; tap < 9; tap++) {
            CP_WAIT0();
            __syncthreads();
            int buf = tap & 1;
            if (tap < 8) {
                int tc = (tap + 1) * 4 + chunk;
                int ob = buf ^ 1;
                #pragma unroll
                for (int j = 0; j < 8; j++) {
                    int idx = t + j * 256;
                    int row = idx >> 3, q = idx & 7;
                    const __half* gs = w216 + (size_t)tc * 16384 + row * 64 + q * 8;
                    uint32_t sd = sbase + W2OFF + ob * W2BUF + row * X1STR + q * 16;
                    cp_async16(sd, gs);
                }
                CP_COMMIT();
            }

            int dr = tap / 3, dc = tap % 3;
            int rowc = dr * 10 + dc + g;
            const char* A  = smem + W2OFF + buf * W2BUF;
            const char* Bh = smem;
            #pragma unroll
            for (int k4 = 0; k4 < 4; k4++) {
                int kb = (k4 * 16 + 2 * tg) * 2;
                unsigned af[2][4];
                #pragma unroll
                for (int mt = 0; mt < 2; mt++) {
                    const char* ar = A + (ocb + mt * 16 + g) * X1STR + kb;
                    af[mt][0] = *(const unsigned*)ar;
                    af[mt][1] = *(const unsigned*)(ar + 8 * X1STR);
                    af[mt][2] = *(const unsigned*)(ar + 16);
                    af[mt][3] = *(const unsigned*)(ar + 8 * X1STR + 16);
                }
                #pragma unroll
                for (int nt = 0; nt < 8; nt++) {
                    const char* br = Bh + (rowc + nt * 10) * X1STR + kb;
                    unsigned b0h = *(const unsigned*)br;
                    unsigned b1h = *(const unsigned*)(br + 16);
                    unsigned b0l = *(const unsigned*)(br + X2ARR);
                    unsigned b1l = *(const unsigned*)(br + X2ARR + 16);
                    #pragma unroll
                    for (int mt = 0; mt < 2; mt++) {
                        mma16816h(acc[mt][nt], af[mt], b0h, b1h);
                        mma16816h(acc[mt][nt], af[mt], b0l, b1l);
                    }
                }
            }
        }
    }

    #pragma unroll
    for (int mt = 0; mt < 2; mt++) {
        int oc_a = ocb + mt * 16 + g;
        int oc_b = oc_a + 8;
        float ba = b2[oc_a], bbv = b2[oc_b];
        float* da = g2buf + ((size_t)blk * C2 + oc_a) * 64;
        float* db = g2buf + ((size_t)blk * C2 + oc_b) * 64;
        float sa = 0.f, qa = 0.f, sb = 0.f, qb = 0.f;
        #pragma unroll
        for (int nt = 0; nt < 8; nt++) {
            int n0 = nt * 8 + tg * 2;
            float2 e0, e1;
            e0.x = fmaxf(acc[mt][nt][0] + ba, 0.f);
            e0.y = fmaxf(acc[mt][nt][1] + ba, 0.f);
            e1.x = fmaxf(acc[mt][nt][2] + bbv, 0.f);
            e1.y = fmaxf(acc[mt][nt][3] + bbv, 0.f);
            sa += e0.x + e0.y; qa += e0.x * e0.x + e0.y * e0.y;
            sb += e1.x + e1.y; qb += e1.x * e1.x + e1.y * e1.y;
            *(float2*)(da + n0) = e0;
            *(float2*)(db + n0) = e1;
        }
        quad_stats(sa, qa, tg, &d_sum2[oc_a], &d_sq2[oc_a]);
        quad_stats(sb, qb, tg, &d_sum2[oc_b], &d_sq2[oc_b]);
    }
}

// ---------------- conv3: 1x1 256->128 via fp16 HMMA 2-pass, 4 blocks/CTA, cp.async W ----------------
#define X3BLK  18432
#define W3OFF  73728
#define SMEM_C3M (W3OFF + 18432)
__global__ __launch_bounds__(256, 1) void conv3m_kernel(const float* __restrict__ b3) {
    extern __shared__ float smf[];
    char* smem = (char*)smf;
    uint32_t sbase = (uint32_t)__cvta_generic_to_shared(smem);
    int t = threadIdx.x, w = t >> 5, lane = t & 31;
    int g = lane >> 2, tg = lane & 3;
    int blk0 = blockIdx.x * 4;
    int mblk = w >> 1;
    int ocb  = (w & 1) * 64;

    float acc[4][8][4];
    #pragma unroll
    for (int mt = 0; mt < 4; mt++)
        #pragma unroll
        for (int nt = 0; nt < 8; nt++)
            #pragma unroll
            for (int e = 0; e < 4; e++) acc[mt][nt][e] = 0.0f;

    int xblk = t >> 6, xic = t & 63;

    for (int chunk = 0; chunk < 4; chunk++) {
        __syncthreads();
        {
            #pragma unroll
            for (int j = 0; j < 4; j++) {
                int idx = t + j * 256;
                int row = idx >> 3, q = idx & 7;
                const __half* gs = w316 + (size_t)chunk * 8192 + row * 64 + q * 8;
                uint32_t sd = sbase + W3OFF + row * X1STR + q * 16;
                cp_async16(sd, gs);
            }
            CP_COMMIT();
        }
        {
            int icg = chunk * 64 + xic;
            const float* src = g2buf + ((size_t)(blk0 + xblk) * C2 + icg) * 64;
            float a = d_a2[icg], bb = d_b2[icg];
            char* xb = smem + xblk * X3BLK + xic * 2;
            #pragma unroll
            for (int j = 0; j < 16; j++) {
                float4 v4 = ((const float4*)src)[j];
                float vals[4] = {v4.x, v4.y, v4.z, v4.w};
                #pragma unroll
                for (int e = 0; e < 4; e++) {
                    int px = j * 4 + e;
                    float xv = a * vals[e] + bb;
                    __half h = __float2half(xv);
                    __half l = __float2half(xv - __half2float(h));
                    *(__half*)(xb + px * X1STR) = h;
                    *(__half*)(xb + X1PART + px * X1STR) = l;
                }
            }
        }
        CP_WAIT0();
        __syncthreads();

        const char* A  = smem + W3OFF;
        const char* Bh = smem + mblk * X3BLK;
        #pragma unroll
        for (int k4 = 0; k4 < 4; k4++) {
            int kb = (k4 * 16 + 2 * tg) * 2;
            unsigned af[4][4];
            #pragma unroll
            for (int mt = 0; mt < 4; mt++) {
                const char* ar = A + (ocb + mt * 16 + g) * X1STR + kb;
                af[mt][0] = *(const unsigned*)ar;
                af[mt][1] = *(const unsigned*)(ar + 8 * X1STR);
                af[mt][2] = *(const unsigned*)(ar + 16);
                af[mt][3] = *(const unsigned*)(ar + 8 * X1STR + 16);
            }
            #pragma unroll
            for (int nt = 0; nt < 8; nt++) {
                const char* br = Bh + (nt * 8 + g) * X1STR + kb;
                unsigned b0h = *(const unsigned*)br;
                unsigned b1h = *(const unsigned*)(br + 16);
                unsigned b0l = *(const unsigned*)(br + X1PART);
                unsigned b1l = *(const unsigned*)(br + X1PART + 16);
                #pragma unroll
                for (int mt = 0; mt < 4; mt++) {
                    mma16816h(acc[mt][nt], af[mt], b0h, b1h);
                    mma16816h(acc[mt][nt], af[mt], b0l, b1l);
                }
            }
        }
    }

    #pragma unroll
    for (int mt = 0; mt < 4; mt++) {
        int oc_a = ocb + mt * 16 + g;
        int oc_b = oc_a + 8;
        float ba = b3[oc_a], bbv = b3[oc_b];
        float* da = g3buf + ((size_t)(blk0 + mblk) * COUT + oc_a) * 64;
        float* db = g3buf + ((size_t)(blk0 + mblk) * COUT + oc_b) * 64;
        float sa = 0.f, qa = 0.f, sb = 0.f, qb = 0.f;
        #pragma unroll
        for (int nt = 0; nt < 8; nt++) {
            int n0 = nt * 8 + tg * 2;
            float2 e0, e1;
            e0.x = fmaxf(acc[mt][nt][0] + ba, 0.f);
            e0.y = fmaxf(acc[mt][nt][1] + ba, 0.f);
            e1.x = fmaxf(acc[mt][nt][2] + bbv, 0.f);
            e1.y = fmaxf(acc[mt][nt][3] + bbv, 0.f);
            sa += e0.x + e0.y; qa += e0.x * e0.x + e0.y * e0.y;
            sb += e1.x + e1.y; qb += e1.x * e1.x + e1.y * e1.y;
            *(float2*)(da + n0) = e0;
            *(float2*)(db + n0) = e1;
        }
        quad_stats(sa, qa, tg, &d_sum3[oc_a], &d_sq3[oc_a]);
        quad_stats(sb, qb, tg, &d_sum3[oc_b], &d_sq3[oc_b]);
    }
}

// ---------------- scatter: BN3(g3) -> image ----------------
__global__ __launch_bounds__(256) void scatter_kernel(const int* __restrict__ abi,
                                                      float* __restrict__ out) {
    int blk = blockIdx.x;
    int n  = abi[blk * 3 + 0];
    int bi = abi[blk * 3 + 1];
    int bj = abi[blk * 3 + 2];
    const float* src = g3buf + (size_t)blk * COUT * 64;
    float* dst = out + (((size_t)(n * COUT)) << 16) + bi * 8 * 256 + bj * 8;
    for (int i = threadIdx.x; i < 2048; i += 256) {
        int c = i >> 4, q = i & 15;
        int r = q >> 1, c4 = (q & 1) * 4;
        float4 v = *reinterpret_cast<const float4*>(src + c * 64 + q * 4);
        float a = d_a3[c], bb = d_b3[c];
        v.x = a * v.x + bb; v.y = a * v.y + bb;
        v.z = a * v.z + bb; v.w = a * v.w + bb;
        *reinterpret_cast<float4*>(dst + (((size_t)c) << 16) + r * 256 + c4) = v;
    }
}

// ---------------- launch ----------------
extern "C" void kernel_launch(void* const* d_in, const int* in_sizes, int n_in,
                              void* d_out, int out_size) {
    const float* x    = (const float*)d_in[0];
    const int*   abi  = (const int*)  d_in[1];
    const float* w_c  = (const float*)d_in[2];
    const float* b_c  = (const float*)d_in[3];
    const float* gm_c = (const float*)d_in[4];
    const float* be_c = (const float*)d_in[5];
    const float* w1   = (const float*)d_in[6];
    const float* b1   = (const float*)d_in[7];
    const float* gm1  = (const float*)d_in[8];
    const float* be1  = (const float*)d_in[9];
    const float* w2   = (const float*)d_in[10];
    const float* b2   = (const float*)d_in[11];
    const float* gm2  = (const float*)d_in[12];
    const float* be2  = (const float*)d_in[13];
    const float* w3   = (const float*)d_in[14];
    const float* b3   = (const float*)d_in[15];
    const float* gm3  = (const float*)d_in[16];
    const float* be3  = (const float*)d_in[17];
    float* out = (float*)d_out;

    cudaFuncSetAttribute(convcm_kernel, cudaFuncAttributeMaxDynamicSharedMemorySize, SMEM_CCM);
    cudaFuncSetAttribute(conv1m_kernel, cudaFuncAttributeMaxDynamicSharedMemorySize, SMEM_C1M);
    cudaFuncSetAttribute(conv2m_kernel, cudaFuncAttributeMaxDynamicSharedMemorySize, SMEM_C2M);
    cudaFuncSetAttribute(conv3m_kernel, cudaFuncAttributeMaxDynamicSharedMemorySize, SMEM_C3M);

    zero_stats_kernel<<<1, 256>>>();
    w2cvt_kernel<<<576, 256>>>(w2);
    w13cvt_kernel<<<64, 256>>>(w1, w3, w_c);

    convcm_kernel<<<4096, 256, SMEM_CCM>>>(x, b_c, out);
    finalize_kernel<<<1, 256>>>(0, gm_c, be_c, 1.0 / 524288.0);
    bnapply_kernel<<<16384, 256>>>(out);

    conv1m_kernel<<<2048, 256, SMEM_C1M>>>(out, abi, b1);
    finalize_kernel<<<1, 256>>>(1, gm1, be1, 1.0 / 262144.0);

    conv2m_kernel<<<4096, 256, SMEM_C2M>>>(b2);
    finalize_kernel<<<1, 256>>>(2, gm2, be2, 1.0 / 262144.0);

    conv3m_kernel<<<1024, 256, SMEM_C3M>>>(b3);
    finalize_kernel<<<1, 256>>>(3, gm3, be3, 1.0 / 262144.0);

    scatter_kernel<<<4096, 256>>>(abi, out);
}

// round 15
// speedup vs baseline: 1.1711x; 1.0034x over previous
#include <cuda_runtime.h>
#include <cuda_bf16.h>
#include <cuda_fp16.h>
#include <math.h>
#include <stdint.h>

#define B_    8
#define CIN   64
#define COUT  128
#define C2    256
#define HW    65536
#define NBLK  4096
#define EPSV  1e-5f

// ---------------- scratch ----------------
__device__ float g1buf[(size_t)NBLK * C2 * 64];
__device__ float g2buf[(size_t)NBLK * C2 * 64];
__device__ float g3buf[(size_t)NBLK * COUT * 64];

// fp16 weights (block convs), bf16 hi/lo for convc
__device__ __half w216[36 * 16384];  // [tap*4+chunk][oc 256][ic 64]
__device__ __half w116[2 * 16384];   // [chunk2][oc 256][ic 64]
__device__ __half w316[4 * 8192];    // [chunk4][oc 128][ic 64]
__device__ __nv_bfloat16 wch[8192];  // [oc 128][ic 64]
__device__ __nv_bfloat16 wcl[8192];

__device__ double d_sum0[COUT], d_sq0[COUT];
__device__ double d_sum1[C2],   d_sq1[C2];
__device__ double d_sum2[C2],   d_sq2[C2];
__device__ double d_sum3[COUT], d_sq3[COUT];
__device__ float  d_a0[COUT], d_b0[COUT];
__device__ float  d_a1[C2],   d_b1[C2];
__device__ float  d_a2[C2],   d_b2[C2];
__device__ float  d_a3[COUT], d_b3[COUT];

#define PKU(x, y) ((unsigned)(x) | ((unsigned)(y) << 16))

// ---------------- MMA helpers ----------------
__device__ __forceinline__ void mma16816(float* d, const unsigned* a, unsigned b0, unsigned b1) {
    asm volatile(
        "mma.sync.aligned.m16n8k16.row.col.f32.bf16.bf16.f32 "
        "{%0,%1,%2,%3}, {%4,%5,%6,%7}, {%8,%9}, {%0,%1,%2,%3};"
        : "+f"(d[0]), "+f"(d[1]), "+f"(d[2]), "+f"(d[3])
        : "r"(a[0]), "r"(a[1]), "r"(a[2]), "r"(a[3]), "r"(b0), "r"(b1));
}
__device__ __forceinline__ void mma16816h(float* d, const unsigned* a, unsigned b0, unsigned b1) {
    asm volatile(
        "mma.sync.aligned.m16n8k16.row.col.f32.f16.f16.f32 "
        "{%0,%1,%2,%3}, {%4,%5,%6,%7}, {%8,%9}, {%0,%1,%2,%3};"
        : "+f"(d[0]), "+f"(d[1]), "+f"(d[2]), "+f"(d[3])
        : "r"(a[0]), "r"(a[1]), "r"(a[2]), "r"(a[3]), "r"(b0), "r"(b1));
}

__device__ __forceinline__ void cp_async16(uint32_t sdst, const void* gsrc) {
    asm volatile("cp.async.cg.shared.global [%0], [%1], 16;" :: "r"(sdst), "l"(gsrc));
}
#define CP_COMMIT() asm volatile("cp.async.commit_group;" ::: "memory")
#define CP_WAIT0()  asm volatile("cp.async.wait_group 0;" ::: "memory")

__device__ __forceinline__ void quad_stats(float s, float s2, int tg,
                                           double* gsum, double* gsq) {
    s  += __shfl_xor_sync(0xffffffffu, s, 1);
    s  += __shfl_xor_sync(0xffffffffu, s, 2);
    s2 += __shfl_xor_sync(0xffffffffu, s2, 1);
    s2 += __shfl_xor_sync(0xffffffffu, s2, 2);
    if (tg == 0) { atomicAdd(gsum, (double)s); atomicAdd(gsq, (double)s2); }
}

// ---------------- utility ----------------
__global__ void zero_stats_kernel() {
    int t = threadIdx.x;
    if (t < COUT) { d_sum0[t] = 0.0; d_sq0[t] = 0.0; d_sum3[t] = 0.0; d_sq3[t] = 0.0; }
    d_sum1[t] = 0.0; d_sq1[t] = 0.0; d_sum2[t] = 0.0; d_sq2[t] = 0.0;
}

__global__ void finalize_kernel(int stage, const float* __restrict__ gamma,
                                const float* __restrict__ beta, double invN) {
    int t = threadIdx.x;
    const double *sum, *sq; float *a, *bsh; int C;
    if (stage == 0)      { sum = d_sum0; sq = d_sq0; a = d_a0; bsh = d_b0; C = COUT; }
    else if (stage == 1) { sum = d_sum1; sq = d_sq1; a = d_a1; bsh = d_b1; C = C2; }
    else if (stage == 2) { sum = d_sum2; sq = d_sq2; a = d_a2; bsh = d_b2; C = C2; }
    else                 { sum = d_sum3; sq = d_sq3; a = d_a3; bsh = d_b3; C = COUT; }
    if (t < C) {
        double mean = sum[t] * invN;
        double var  = sq[t] * invN - mean * mean;
        float v = fmaxf((float)var, 0.0f);
        float av = gamma[t] * rsqrtf(v + EPSV);
        a[t] = av;
        bsh[t] = beta[t] - av * (float)mean;
    }
}

// ---------------- weight converts ----------------
__global__ __launch_bounds__(256) void w2cvt_kernel(const float* __restrict__ w2) {
    int i4 = blockIdx.x * 256 + threadIdx.x;
    int ic0 = (i4 & 15) * 4;
    int oc  = (i4 >> 4) & 255;
    int tc  = i4 >> 12;
    int tap = tc >> 2, chunk = tc & 3;
    #pragma unroll
    for (int e = 0; e < 4; e++) {
        int ic = ic0 + e;
        float v = w2[(size_t)oc * 2304 + (chunk * 64 + ic) * 9 + tap];
        w216[(size_t)tc * 16384 + oc * 64 + ic] = __float2half(v);
    }
}

__global__ __launch_bounds__(256) void w13cvt_kernel(const float* __restrict__ w1,
                                                     const float* __restrict__ w3,
                                                     const float* __restrict__ wc) {
    int i = blockIdx.x * 256 + threadIdx.x;   // 0..16383
    {
        #pragma unroll
        for (int e = 0; e < 2; e++) {
            int idx = i * 2 + e;
            int ic = idx & 63, oc = (idx >> 6) & 255, ch = idx >> 14;
            w116[idx] = __float2half(w1[(size_t)oc * 128 + ch * 64 + ic]);
        }
    }
    {
        #pragma unroll
        for (int e = 0; e < 2; e++) {
            int idx = i * 2 + e;
            int ic = idx & 63, oc = (idx >> 6) & 127, ch = idx >> 13;
            w316[idx] = __float2half(w3[(size_t)oc * 256 + ch * 64 + ic]);
        }
    }
    if (i < 8192) {
        float v = wc[i];
        __nv_bfloat16 h = __float2bfloat16(v);
        wch[i] = h;
        wcl[i] = __float2bfloat16(v - __bfloat162float(h));
    }
}

// ---------------- convc: 1x1 64->128 via bf16 HMMA 3-pass, 128 px/CTA, fused stats ----------------
#define XCSTR  144
#define XCPART 18432
#define WCOFF  36864
#define WCPART 18432
#define SMEM_CCM (WCOFF + 2 * WCPART)
__global__ __launch_bounds__(256, 2) void convcm_kernel(const float* __restrict__ x,
                                                        const float* __restrict__ bc,
                                                        float* __restrict__ out) {
    extern __shared__ float smf[];
    char* smem = (char*)smf;
    int t = threadIdx.x, w = t >> 5, lane = t & 31;
    int g = lane >> 2, tg = lane & 3;
    int b  = blockIdx.x >> 9;
    int p0 = (blockIdx.x & 511) << 7;
    int ocb = (w & 1) * 64;
    int pxb = (w >> 1) * 32;

    {
        int icp = t & 31, pxg = t >> 5;
        const float* s0 = x + (((size_t)(b * CIN + icp * 2)) << 16) + p0 + pxg * 16;
        const float* s1 = s0 + HW;
        char* xb = smem + icp * 4;
        #pragma unroll
        for (int q = 0; q < 4; q++) {
            float4 u0 = ((const float4*)s0)[q];
            float4 u1 = ((const float4*)s1)[q];
            float v0[4] = {u0.x, u0.y, u0.z, u0.w};
            float v1[4] = {u1.x, u1.y, u1.z, u1.w};
            #pragma unroll
            for (int e = 0; e < 4; e++) {
                int px = pxg * 16 + q * 4 + e;
                __nv_bfloat16 h0 = __float2bfloat16(v0[e]);
                __nv_bfloat16 h1 = __float2bfloat16(v1[e]);
                __nv_bfloat16 l0 = __float2bfloat16(v0[e] - __bfloat162float(h0));
                __nv_bfloat16 l1 = __float2bfloat16(v1[e] - __bfloat162float(h1));
                *(unsigned*)(xb + px * XCSTR) =
                    PKU(__bfloat16_as_ushort(h0), __bfloat16_as_ushort(h1));
                *(unsigned*)(xb + XCPART + px * XCSTR) =
                    PKU(__bfloat16_as_ushort(l0), __bfloat16_as_ushort(l1));
            }
        }
    }
    {
        int part = t >> 7, oc = t & 127;
        const __nv_bfloat16* ws = (part ? wcl : wch) + oc * 64;
        const uint4* s = (const uint4*)ws;
        uint4* d = (uint4*)(smem + WCOFF + part * WCPART + oc * XCSTR);
        #pragma unroll
        for (int q = 0; q < 8; q++) d[q] = s[q];
    }
    __syncthreads();

    float acc[4][4][4];
    #pragma unroll
    for (int mt = 0; mt < 4; mt++)
        #pragma unroll
        for (int nt = 0; nt < 4; nt++)
            #pragma unroll
            for (int e = 0; e < 4; e++) acc[mt][nt][e] = 0.0f;

    #pragma unroll 1
    for (int pass = 0; pass < 3; pass++) {
        const char* A  = smem + WCOFF + ((pass == 1) ? WCPART : 0);
        const char* Bp = smem + ((pass == 2) ? XCPART : 0);
        #pragma unroll
        for (int k4 = 0; k4 < 4; k4++) {
            int kb = (k4 * 16 + 2 * tg) * 2;
            unsigned af[4][4];
            #pragma unroll
            for (int mt = 0; mt < 4; mt++) {
                const char* ar = A + (ocb + mt * 16 + g) * XCSTR + kb;
                af[mt][0] = *(const unsigned*)ar;
                af[mt][1] = *(const unsigned*)(ar + 8 * XCSTR);
                af[mt][2] = *(const unsigned*)(ar + 16);
                af[mt][3] = *(const unsigned*)(ar + 8 * XCSTR + 16);
            }
            #pragma unroll
            for (int nt = 0; nt < 4; nt++) {
                const char* br = Bp + (pxb + nt * 8 + g) * XCSTR + kb;
                unsigned b0 = *(const unsigned*)br;
                unsigned b1v = *(const unsigned*)(br + 16);
                #pragma unroll
                for (int mt = 0; mt < 4; mt++)
                    mma16816(acc[mt][nt], af[mt], b0, b1v);
            }
        }
    }

    float* dstb = out + (((size_t)(b * COUT)) << 16) + p0;
    #pragma unroll
    for (int mt = 0; mt < 4; mt++) {
        int oc_a = ocb + mt * 16 + g;
        int oc_b = oc_a + 8;
        float ba = bc[oc_a], bbv = bc[oc_b];
        float* da = dstb + (((size_t)oc_a) << 16) + pxb;
        float* db = dstb + (((size_t)oc_b) << 16) + pxb;
        float sa = 0.f, qa = 0.f, sb = 0.f, qb = 0.f;
        #pragma unroll
        for (int nt = 0; nt < 4; nt++) {
            int n0 = nt * 8 + tg * 2;
            float2 e0, e1;
            e0.x = fmaxf(acc[mt][nt][0] + ba, 0.f);
            e0.y = fmaxf(acc[mt][nt][1] + ba, 0.f);
            e1.x = fmaxf(acc[mt][nt][2] + bbv, 0.f);
            e1.y = fmaxf(acc[mt][nt][3] + bbv, 0.f);
            sa += e0.x + e0.y; qa += e0.x * e0.x + e0.y * e0.y;
            sb += e1.x + e1.y; qb += e1.x * e1.x + e1.y * e1.y;
            *(float2*)(da + n0) = e0;
            *(float2*)(db + n0) = e1;
        }
        quad_stats(sa, qa, tg, &d_sum0[oc_a], &d_sq0[oc_a]);
        quad_stats(sb, qb, tg, &d_sum0[oc_b], &d_sq0[oc_b]);
    }
}

__global__ __launch_bounds__(256) void bnapply_kernel(float* __restrict__ y) {
    int nth = gridDim.x * blockDim.x;
    int total = (B_ * COUT * HW) / 4;
    for (int i = blockIdx.x * blockDim.x + threadIdx.x; i < total; i += nth) {
        int c = (i >> 14) & 127;
        float4 v = reinterpret_cast<float4*>(y)[i];
        float a = d_a0[c], bb = d_b0[c];
        v.x = a * v.x + bb; v.y = a * v.y + bb;
        v.z = a * v.z + bb; v.w = a * v.w + bb;
        reinterpret_cast<float4*>(y)[i] = v;
    }
}

// ---------------- conv1: gather + 1x1 128->256, BN0 folded into X build ----------------
#define X1STR  144
#define X1PART 9216
#define X1BLK  18432
#define W1OFF  36864
#define SMEM_C1M (W1OFF + 36864)
__global__ __launch_bounds__(256, 1) void conv1m_kernel(const float* __restrict__ xraw,
                                                        const int* __restrict__ abi,
                                                        const float* __restrict__ b1) {
    extern __shared__ float smf[];
    char* smem = (char*)smf;
    uint32_t sbase = (uint32_t)__cvta_generic_to_shared(smem);
    int t = threadIdx.x, w = t >> 5, lane = t & 31;
    int g = lane >> 2, tg = lane & 3;
    int blk0 = blockIdx.x * 2;
    int mblk = w >> 2;
    int ocb  = (w & 3) * 64;

    float acc[4][8][4];
    #pragma unroll
    for (int mt = 0; mt < 4; mt++)
        #pragma unroll
        for (int nt = 0; nt < 8; nt++)
            #pragma unroll
            for (int e = 0; e < 4; e++) acc[mt][nt][e] = 0.0f;

    int brow = t >> 1, bsub = t & 1;
    int xblk = brow >> 6, xic = brow & 63;
    int n_  = abi[(blk0 + xblk) * 3 + 0];
    int bi_ = abi[(blk0 + xblk) * 3 + 1];
    int bj_ = abi[(blk0 + xblk) * 3 + 2];
    const float* gsrc0 = xraw + (((size_t)(n_ * COUT)) << 16) + bi_ * 2048 + bj_ * 8;

    for (int chunk = 0; chunk < 2; chunk++) {
        __syncthreads();
        {
            #pragma unroll
            for (int j = 0; j < 8; j++) {
                int idx = t + j * 256;
                int row = idx >> 3, q = idx & 7;
                const __half* gs = w116 + (size_t)chunk * 16384 + row * 64 + q * 8;
                uint32_t sd = sbase + W1OFF + row * X1STR + q * 16;
                cp_async16(sd, gs);
            }
            CP_COMMIT();
        }
        {
            int icg = chunk * 64 + xic;
            const float* src = gsrc0 + (((size_t)icg) << 16) + bsub * 4 * 256;
            float a0 = d_a0[icg], c0 = d_b0[icg];   // BN0 folded
            char* xb = smem + xblk * X1BLK + xic * 2;
            #pragma unroll
            for (int r4 = 0; r4 < 4; r4++) {
                float4 u  = *reinterpret_cast<const float4*>(src + r4 * 256);
                float4 v2 = *reinterpret_cast<const float4*>(src + r4 * 256 + 4);
                float vals[8] = {u.x, u.y, u.z, u.w, v2.x, v2.y, v2.z, v2.w};
                int px0 = bsub * 32 + r4 * 8;
                #pragma unroll
                for (int e = 0; e < 8; e++) {
                    float xv = a0 * vals[e] + c0;
                    __half h = __float2half(xv);
                    __half l = __float2half(xv - __half2float(h));
                    *(__half*)(xb + (px0 + e) * X1STR) = h;
                    *(__half*)(xb + X1PART + (px0 + e) * X1STR) = l;
                }
            }
        }
        CP_WAIT0();
        __syncthreads();

        const char* A  = smem + W1OFF;
        const char* Bh = smem + mblk * X1BLK;
        #pragma unroll
        for (int k4 = 0; k4 < 4; k4++) {
            int kb = (k4 * 16 + 2 * tg) * 2;
            unsigned af[4][4];
            #pragma unroll
            for (int mt = 0; mt < 4; mt++) {
                const char* ar = A + (ocb + mt * 16 + g) * X1STR + kb;
                af[mt][0] = *(const unsigned*)ar;
                af[mt][1] = *(const unsigned*)(ar + 8 * X1STR);
                af[mt][2] = *(const unsigned*)(ar + 16);
                af[mt][3] = *(const unsigned*)(ar + 8 * X1STR + 16);
            }
            #pragma unroll
            for (int nt = 0; nt < 8; nt++) {
                const char* br = Bh + (nt * 8 + g) * X1STR + kb;
                unsigned b0h = *(const unsigned*)br;
                unsigned b1h = *(const unsigned*)(br + 16);
                unsigned b0l = *(const unsigned*)(br + X1PART);
                unsigned b1l = *(const unsigned*)(br + X1PART + 16);
                #pragma unroll
                for (int mt = 0; mt < 4; mt++) {
                    mma16816h(acc[mt][nt], af[mt], b0h, b1h);
                    mma16816h(acc[mt][nt], af[mt], b0l, b1l);
                }
            }
        }
    }

    #pragma unroll
    for (int mt = 0; mt < 4; mt++) {
        int oc_a = ocb + mt * 16 + g;
        int oc_b = oc_a + 8;
        float ba = b1[oc_a], bbv = b1[oc_b];
        float* da = g1buf + ((size_t)(blk0 + mblk) * C2 + oc_a) * 64;
        float* db = g1buf + ((size_t)(blk0 + mblk) * C2 + oc_b) * 64;
        float sa = 0.f, qa = 0.f, sb = 0.f, qb = 0.f;
        #pragma unroll
        for (int nt = 0; nt < 8; nt++) {
            int n0 = nt * 8 + tg * 2;
            float2 e0, e1;
            e0.x = fmaxf(acc[mt][nt][0] + ba, 0.f);
            e0.y = fmaxf(acc[mt][nt][1] + ba, 0.f);
            e1.x = fmaxf(acc[mt][nt][2] + bbv, 0.f);
            e1.y = fmaxf(acc[mt][nt][3] + bbv, 0.f);
            sa += e0.x + e0.y; qa += e0.x * e0.x + e0.y * e0.y;
            sb += e1.x + e1.y; qb += e1.x * e1.x + e1.y * e1.y;
            *(float2*)(da + n0) = e0;
            *(float2*)(db + n0) = e1;
        }
        quad_stats(sa, qa, tg, &d_sum1[oc_a], &d_sq1[oc_a]);
        quad_stats(sb, qb, tg, &d_sum1[oc_b], &d_sq1[oc_b]);
    }
}

// ---------------- conv2: 3x3 via fp16 HMMA 2-pass, padded-2D X, cp.async dbuf W ----------------
#define X2ARR  14400
#define X2BLK  28800
#define W2OFF  57600
#define W2BUF  36864
#define SMEM_C2M (W2OFF + 2 * W2BUF)
__global__ __launch_bounds__(256, 1) void conv2m_kernel(const float* __restrict__ b2) {
    extern __shared__ float smf[];
    char* smem = (char*)smf;
    uint32_t sbase = (uint32_t)__cvta_generic_to_shared(smem);
    int t = threadIdx.x, w = t >> 5, lane = t & 31;
    int g = lane >> 2, tg = lane & 3;
    int blk0 = blockIdx.x * 2;
    int mblk = w >> 2;
    int ocb  = (w & 3) * 64;

    float acc[4][8][4];
    #pragma unroll
    for (int mt = 0; mt < 4; mt++)
        #pragma unroll
        for (int nt = 0; nt < 8; nt++)
            #pragma unroll
            for (int e = 0; e < 4; e++) acc[mt][nt][e] = 0.0f;

    for (int i = t; i < W2OFF / 16; i += 256) ((uint4*)smem)[i] = make_uint4(0, 0, 0, 0);

    int xblk = t >> 7;
    int icp  = (t >> 2) & 31;
    int pxg  = t & 3;

    for (int chunk = 0; chunk < 4; chunk++) {
        __syncthreads();
        {
            int tc = chunk;
            #pragma unroll
            for (int j = 0; j < 8; j++) {
                int idx = t + j * 256;
                int row = idx >> 3, q = idx & 7;
                const __half* gs = w216 + (size_t)tc * 16384 + row * 64 + q * 8;
                uint32_t sd = sbase + W2OFF + row * X1STR + q * 16;
                cp_async16(sd, gs);
            }
            CP_COMMIT();
        }
        {
            int ic0 = chunk * 64 + icp * 2;
            const float* s0 = g1buf + ((size_t)(blk0 + xblk) * C2 + ic0) * 64 + pxg * 16;
            const float* s1 = s0 + 64;
            float a0 = d_a1[ic0],     c0 = d_b1[ic0];
            float a1 = d_a1[ic0 + 1], c1 = d_b1[ic0 + 1];
            char* xb = smem + xblk * X2BLK + icp * 4;
            #pragma unroll
            for (int q = 0; q < 4; q++) {
                float4 u0 = ((const float4*)s0)[q];
                float4 u1 = ((const float4*)s1)[q];
                float v0[4] = {u0.x, u0.y, u0.z, u0.w};
                float v1[4] = {u1.x, u1.y, u1.z, u1.w};
                #pragma unroll
                for (int e = 0; e < 4; e++) {
                    int p = pxg * 16 + q * 4 + e;
                    int row = ((p >> 3) + 1) * 10 + (p & 7) + 1;
                    float x0 = a0 * v0[e] + c0;
                    float x1 = a1 * v1[e] + c1;
                    __half h0 = __float2half(x0);
                    __half h1 = __float2half(x1);
                    __half l0 = __float2half(x0 - __half2float(h0));
                    __half l1 = __float2half(x1 - __half2float(h1));
                    *(unsigned*)(xb + row * X1STR) =
                        PKU(__half_as_ushort(h0), __half_as_ushort(h1));
                    *(unsigned*)(xb + X2ARR + row * X1STR) =
                        PKU(__half_as_ushort(l0), __half_as_ushort(l1));
                }
            }
        }

        for (int tap = 0; tap < 9; tap++) {
            CP_WAIT0();
            __syncthreads();
            int buf = tap & 1;
            if (tap < 8) {
                int tc = (tap + 1) * 4 + chunk;
                int ob = buf ^ 1;
                #pragma unroll
                for (int j = 0; j < 8; j++) {
                    int idx = t + j * 256;
                    int row = idx >> 3, q = idx & 7;
                    const __half* gs = w216 + (size_t)tc * 16384 + row * 64 + q * 8;
                    uint32_t sd = sbase + W2OFF + ob * W2BUF + row * X1STR + q * 16;
                    cp_async16(sd, gs);
                }
                CP_COMMIT();
            }

            int dr = tap / 3, dc = tap % 3;
            int rowc = dr * 10 + dc + g;
            const char* A  = smem + W2OFF + buf * W2BUF;
            const char* Bh = smem + mblk * X2BLK;
            #pragma unroll
            for (int k4 = 0; k4 < 4; k4++) {
                int kb = (k4 * 16 + 2 * tg) * 2;
                unsigned af[4][4];
                #pragma unroll
                for (int mt = 0; mt < 4; mt++) {
                    const char* ar = A + (ocb + mt * 16 + g) * X1STR + kb;
                    af[mt][0] = *(const unsigned*)ar;
                    af[mt][1] = *(const unsigned*)(ar + 8 * X1STR);
                    af[mt][2] = *(const unsigned*)(ar + 16);
                    af[mt][3] = *(const unsigned*)(ar + 8 * X1STR + 16);
                }
                #pragma unroll
                for (int nt = 0; nt < 8; nt++) {
                    const char* br = Bh + (rowc + nt * 10) * X1STR + kb;
                    unsigned b0h = *(const unsigned*)br;
                    unsigned b1h = *(const unsigned*)(br + 16);
                    unsigned b0l = *(const unsigned*)(br + X2ARR);
                    unsigned b1l = *(const unsigned*)(br + X2ARR + 16);
                    #pragma unroll
                    for (int mt = 0; mt < 4; mt++) {
                        mma16816h(acc[mt][nt], af[mt], b0h, b1h);
                        mma16816h(acc[mt][nt], af[mt], b0l, b1l);
                    }
                }
            }
        }
    }

    #pragma unroll
    for (int mt = 0; mt < 4; mt++) {
        int oc_a = ocb + mt * 16 + g;
        int oc_b = oc_a + 8;
        float ba = b2[oc_a], bbv = b2[oc_b];
        float* da = g2buf + ((size_t)(blk0 + mblk) * C2 + oc_a) * 64;
        float* db = g2buf + ((size_t)(blk0 + mblk) * C2 + oc_b) * 64;
        float sa = 0.f, qa = 0.f, sb = 0.f, qb = 0.f;
        #pragma unroll
        for (int nt = 0; nt < 8; nt++) {
            int n0 = nt * 8 + tg * 2;
            float2 e0, e1;
            e0.x = fmaxf(acc[mt][nt][0] + ba, 0.f);
            e0.y = fmaxf(acc[mt][nt][1] + ba, 0.f);
            e1.x = fmaxf(acc[mt][nt][2] + bbv, 0.f);
            e1.y = fmaxf(acc[mt][nt][3] + bbv, 0.f);
            sa += e0.x + e0.y; qa += e0.x * e0.x + e0.y * e0.y;
            sb += e1.x + e1.y; qb += e1.x * e1.x + e1.y * e1.y;
            *(float2*)(da + n0) = e0;
            *(float2*)(db + n0) = e1;
        }
        quad_stats(sa, qa, tg, &d_sum2[oc_a], &d_sq2[oc_a]);
        quad_stats(sb, qb, tg, &d_sum2[oc_b], &d_sq2[oc_b]);
    }
}

// ---------------- conv3: 1x1 256->128 via fp16 HMMA 2-pass, 4 blocks/CTA, cp.async W ----------------
#define X3BLK  18432
#define W3OFF  73728
#define SMEM_C3M (W3OFF + 18432)
__global__ __launch_bounds__(256, 1) void conv3m_kernel(const float* __restrict__ b3) {
    extern __shared__ float smf[];
    char* smem = (char*)smf;
    uint32_t sbase = (uint32_t)__cvta_generic_to_shared(smem);
    int t = threadIdx.x, w = t >> 5, lane = t & 31;
    int g = lane >> 2, tg = lane & 3;
    int blk0 = blockIdx.x * 4;
    int mblk = w >> 1;
    int ocb  = (w & 1) * 64;

    float acc[4][8][4];
    #pragma unroll
    for (int mt = 0; mt < 4; mt++)
        #pragma unroll
        for (int nt = 0; nt < 8; nt++)
            #pragma unroll
            for (int e = 0; e < 4; e++) acc[mt][nt][e] = 0.0f;

    int xblk = t >> 6, xic = t & 63;

    for (int chunk = 0; chunk < 4; chunk++) {
        __syncthreads();
        {
            #pragma unroll
            for (int j = 0; j < 4; j++) {
                int idx = t + j * 256;
                int row = idx >> 3, q = idx & 7;
                const __half* gs = w316 + (size_t)chunk * 8192 + row * 64 + q * 8;
                uint32_t sd = sbase + W3OFF + row * X1STR + q * 16;
                cp_async16(sd, gs);
            }
            CP_COMMIT();
        }
        {
            int icg = chunk * 64 + xic;
            const float* src = g2buf + ((size_t)(blk0 + xblk) * C2 + icg) * 64;
            float a = d_a2[icg], bb = d_b2[icg];
            char* xb = smem + xblk * X3BLK + xic * 2;
            #pragma unroll
            for (int j = 0; j < 16; j++) {
                float4 v4 = ((const float4*)src)[j];
                float vals[4] = {v4.x, v4.y, v4.z, v4.w};
                #pragma unroll
                for (int e = 0; e < 4; e++) {
                    int px = j * 4 + e;
                    float xv = a * vals[e] + bb;
                    __half h = __float2half(xv);
                    __half l = __float2half(xv - __half2float(h));
                    *(__half*)(xb + px * X1STR) = h;
                    *(__half*)(xb + X1PART + px * X1STR) = l;
                }
            }
        }
        CP_WAIT0();
        __syncthreads();

        const char* A  = smem + W3OFF;
        const char* Bh = smem + mblk * X3BLK;
        #pragma unroll
        for (int k4 = 0; k4 < 4; k4++) {
            int kb = (k4 * 16 + 2 * tg) * 2;
            unsigned af[4][4];
            #pragma unroll
            for (int mt = 0; mt < 4; mt++) {
                const char* ar = A + (ocb + mt * 16 + g) * X1STR + kb;
                af[mt][0] = *(const unsigned*)ar;
                af[mt][1] = *(const unsigned*)(ar + 8 * X1STR);
                af[mt][2] = *(const unsigned*)(ar + 16);
                af[mt][3] = *(const unsigned*)(ar + 8 * X1STR + 16);
            }
            #pragma unroll
            for (int nt = 0; nt < 8; nt++) {
                const char* br = Bh + (nt * 8 + g) * X1STR + kb;
                unsigned b0h = *(const unsigned*)br;
                unsigned b1h = *(const unsigned*)(br + 16);
                unsigned b0l = *(const unsigned*)(br + X1PART);
                unsigned b1l = *(const unsigned*)(br + X1PART + 16);
                #pragma unroll
                for (int mt = 0; mt < 4; mt++) {
                    mma16816h(acc[mt][nt], af[mt], b0h, b1h);
                    mma16816h(acc[mt][nt], af[mt], b0l, b1l);
                }
            }
        }
    }

    #pragma unroll
    for (int mt = 0; mt < 4; mt++) {
        int oc_a = ocb + mt * 16 + g;
        int oc_b = oc_a + 8;
        float ba = b3[oc_a], bbv = b3[oc_b];
        float* da = g3buf + ((size_t)(blk0 + mblk) * COUT + oc_a) * 64;
        float* db = g3buf + ((size_t)(blk0 + mblk) * COUT + oc_b) * 64;
        float sa = 0.f, qa = 0.f, sb = 0.f, qb = 0.f;
        #pragma unroll
        for (int nt = 0; nt < 8; nt++) {
            int n0 = nt * 8 + tg * 2;
            float2 e0, e1;
            e0.x = fmaxf(acc[mt][nt][0] + ba, 0.f);
            e0.y = fmaxf(acc[mt][nt][1] + ba, 0.f);
            e1.x = fmaxf(acc[mt][nt][2] + bbv, 0.f);
            e1.y = fmaxf(acc[mt][nt][3] + bbv, 0.f);
            sa += e0.x + e0.y; qa += e0.x * e0.x + e0.y * e0.y;
            sb += e1.x + e1.y; qb += e1.x * e1.x + e1.y * e1.y;
            *(float2*)(da + n0) = e0;
            *(float2*)(db + n0) = e1;
        }
        quad_stats(sa, qa, tg, &d_sum3[oc_a], &d_sq3[oc_a]);
        quad_stats(sb, qb, tg, &d_sum3[oc_b], &d_sq3[oc_b]);
    }
}

// ---------------- scatter: BN3(g3) -> image ----------------
__global__ __launch_bounds__(256) void scatter_kernel(const int* __restrict__ abi,
                                                      float* __restrict__ out) {
    int blk = blockIdx.x;
    int n  = abi[blk * 3 + 0];
    int bi = abi[blk * 3 + 1];
    int bj = abi[blk * 3 + 2];
    const float* src = g3buf + (size_t)blk * COUT * 64;
    float* dst = out + (((size_t)(n * COUT)) << 16) + bi * 8 * 256 + bj * 8;
    for (int i = threadIdx.x; i < 2048; i += 256) {
        int c = i >> 4, q = i & 15;
        int r = q >> 1, c4 = (q & 1) * 4;
        float4 v = *reinterpret_cast<const float4*>(src + c * 64 + q * 4);
        float a = d_a3[c], bb = d_b3[c];
        v.x = a * v.x + bb; v.y = a * v.y + bb;
        v.z = a * v.z + bb; v.w = a * v.w + bb;
        *reinterpret_cast<float4*>(dst + (((size_t)c) << 16) + r * 256 + c4) = v;
    }
}

// ---------------- launch ----------------
extern "C" void kernel_launch(void* const* d_in, const int* in_sizes, int n_in,
                              void* d_out, int out_size) {
    const float* x    = (const float*)d_in[0];
    const int*   abi  = (const int*)  d_in[1];
    const float* w_c  = (const float*)d_in[2];
    const float* b_c  = (const float*)d_in[3];
    const float* gm_c = (const float*)d_in[4];
    const float* be_c = (const float*)d_in[5];
    const float* w1   = (const float*)d_in[6];
    const float* b1   = (const float*)d_in[7];
    const float* gm1  = (const float*)d_in[8];
    const float* be1  = (const float*)d_in[9];
    const float* w2   = (const float*)d_in[10];
    const float* b2   = (const float*)d_in[11];
    const float* gm2  = (const float*)d_in[12];
    const float* be2  = (const float*)d_in[13];
    const float* w3   = (const float*)d_in[14];
    const float* b3   = (const float*)d_in[15];
    const float* gm3  = (const float*)d_in[16];
    const float* be3  = (const float*)d_in[17];
    float* out = (float*)d_out;

    static cudaStream_t s2 = nullptr;
    static cudaEvent_t evf = nullptr, evj = nullptr;
    if (s2 == nullptr) {
        cudaStreamCreateWithFlags(&s2, cudaStreamNonBlocking);
        cudaEventCreateWithFlags(&evf, cudaEventDisableTiming);
        cudaEventCreateWithFlags(&evj, cudaEventDisableTiming);
    }

    cudaFuncSetAttribute(convcm_kernel, cudaFuncAttributeMaxDynamicSharedMemorySize, SMEM_CCM);
    cudaFuncSetAttribute(conv1m_kernel, cudaFuncAttributeMaxDynamicSharedMemorySize, SMEM_C1M);
    cudaFuncSetAttribute(conv2m_kernel, cudaFuncAttributeMaxDynamicSharedMemorySize, SMEM_C2M);
    cudaFuncSetAttribute(conv3m_kernel, cudaFuncAttributeMaxDynamicSharedMemorySize, SMEM_C3M);

    zero_stats_kernel<<<1, 256>>>();
    w2cvt_kernel<<<576, 256>>>(w2);
    w13cvt_kernel<<<64, 256>>>(w1, w3, w_c);

    convcm_kernel<<<4096, 256, SMEM_CCM>>>(x, b_c, out);
    finalize_kernel<<<1, 256>>>(0, gm_c, be_c, 1.0 / 524288.0);

    // conv1 reads the raw (pre-BN0) image and folds BN0 into its X build
    conv1m_kernel<<<2048, 256, SMEM_C1M>>>(out, abi, b1);

    // fork: BN0-apply the full image on a side stream (overlaps conv2/conv3)
    cudaEventRecord(evf, 0);
    cudaStreamWaitEvent(s2, evf, 0);
    bnapply_kernel<<<16384, 256, 0, s2>>>(out);
    cudaEventRecord(evj, s2);

    finalize_kernel<<<1, 256>>>(1, gm1, be1, 1.0 / 262144.0);

    conv2m_kernel<<<2048, 256, SMEM_C2M>>>(b2);
    finalize_kernel<<<1, 256>>>(2, gm2, be2, 1.0 / 262144.0);

    conv3m_kernel<<<1024, 256, SMEM_C3M>>>(b3);
    finalize_kernel<<<1, 256>>>(3, gm3, be3, 1.0 / 262144.0);

    // join before scatter overwrites block regions of out
    cudaStreamWaitEvent(0, evj, 0);
    scatter_kernel<<<4096, 256>>>(abi, out);
}

// round 16
// speedup vs baseline: 1.5431x; 1.3177x over previous
#include <cuda_runtime.h>
#include <cuda_bf16.h>
#include <cuda_fp16.h>
#include <math.h>
#include <stdint.h>

#define B_    8
#define CIN   64
#define COUT  128
#define C2    256
#define HW    65536
#define NBLK  4096
#define EPSV  1e-5f

// ---------------- scratch ----------------
__device__ float g1buf[(size_t)NBLK * C2 * 64];
__device__ float g2buf[(size_t)NBLK * C2 * 64];
__device__ float g3buf[(size_t)NBLK * COUT * 64];

// fp16 weights (block convs), bf16 hi/lo for convc
__device__ __half w216[36 * 16384];  // [tap*4+chunk][oc 256][ic 64]
__device__ __half w116[2 * 16384];   // [chunk2][oc 256][ic 64]
__device__ __half w316[4 * 8192];    // [chunk4][oc 128][ic 64]
__device__ __nv_bfloat16 wch[8192];  // [oc 128][ic 64]
__device__ __nv_bfloat16 wcl[8192];

__device__ double d_sum0[COUT], d_sq0[COUT];
__device__ double d_sum1[C2],   d_sq1[C2];
__device__ double d_sum2[C2],   d_sq2[C2];
__device__ double d_sum3[COUT], d_sq3[COUT];
__device__ float  d_a0[COUT], d_b0[COUT];
__device__ float  d_a1[C2],   d_b1[C2];
__device__ float  d_a2[C2],   d_b2[C2];
__device__ float  d_a3[COUT], d_b3[COUT];

#define PKU(x, y) ((unsigned)(x) | ((unsigned)(y) << 16))

// ---------------- MMA helpers ----------------
__device__ __forceinline__ void mma16816(float* d, const unsigned* a, unsigned b0, unsigned b1) {
    asm volatile(
        "mma.sync.aligned.m16n8k16.row.col.f32.bf16.bf16.f32 "
        "{%0,%1,%2,%3}, {%4,%5,%6,%7}, {%8,%9}, {%0,%1,%2,%3};"
        : "+f"(d[0]), "+f"(d[1]), "+f"(d[2]), "+f"(d[3])
        : "r"(a[0]), "r"(a[1]), "r"(a[2]), "r"(a[3]), "r"(b0), "r"(b1));
}
__device__ __forceinline__ void mma16816h(float* d, const unsigned* a, unsigned b0, unsigned b1) {
    asm volatile(
        "mma.sync.aligned.m16n8k16.row.col.f32.f16.f16.f32 "
        "{%0,%1,%2,%3}, {%4,%5,%6,%7}, {%8,%9}, {%0,%1,%2,%3};"
        : "+f"(d[0]), "+f"(d[1]), "+f"(d[2]), "+f"(d[3])
        : "r"(a[0]), "r"(a[1]), "r"(a[2]), "r"(a[3]), "r"(b0), "r"(b1));
}

__device__ __forceinline__ void cp_async16(uint32_t sdst, const void* gsrc) {
    asm volatile("cp.async.cg.shared.global [%0], [%1], 16;" :: "r"(sdst), "l"(gsrc));
}
#define CP_COMMIT() asm volatile("cp.async.commit_group;" ::: "memory")
#define CP_WAIT0()  asm volatile("cp.async.wait_group 0;" ::: "memory")

__device__ __forceinline__ void quad_stats(float s, float s2, int tg,
                                           double* gsum, double* gsq) {
    s  += __shfl_xor_sync(0xffffffffu, s, 1);
    s  += __shfl_xor_sync(0xffffffffu, s, 2);
    s2 += __shfl_xor_sync(0xffffffffu, s2, 1);
    s2 += __shfl_xor_sync(0xffffffffu, s2, 2);
    if (tg == 0) { atomicAdd(gsum, (double)s); atomicAdd(gsq, (double)s2); }
}

// ---------------- utility ----------------
__global__ void zero_stats_kernel() {
    int t = threadIdx.x;
    if (t < COUT) { d_sum0[t] = 0.0; d_sq0[t] = 0.0; d_sum3[t] = 0.0; d_sq3[t] = 0.0; }
    d_sum1[t] = 0.0; d_sq1[t] = 0.0; d_sum2[t] = 0.0; d_sq2[t] = 0.0;
}

__global__ void finalize_kernel(int stage, const float* __restrict__ gamma,
                                const float* __restrict__ beta, double invN) {
    int t = threadIdx.x;
    const double *sum, *sq; float *a, *bsh; int C;
    if (stage == 0)      { sum = d_sum0; sq = d_sq0; a = d_a0; bsh = d_b0; C = COUT; }
    else if (stage == 1) { sum = d_sum1; sq = d_sq1; a = d_a1; bsh = d_b1; C = C2; }
    else if (stage == 2) { sum = d_sum2; sq = d_sq2; a = d_a2; bsh = d_b2; C = C2; }
    else                 { sum = d_sum3; sq = d_sq3; a = d_a3; bsh = d_b3; C = COUT; }
    if (t < C) {
        double mean = sum[t] * invN;
        double var  = sq[t] * invN - mean * mean;
        float v = fmaxf((float)var, 0.0f);
        float av = gamma[t] * rsqrtf(v + EPSV);
        a[t] = av;
        bsh[t] = beta[t] - av * (float)mean;
    }
}

// ---------------- weight converts ----------------
__global__ __launch_bounds__(256) void w2cvt_kernel(const float* __restrict__ w2) {
    int i4 = blockIdx.x * 256 + threadIdx.x;
    int ic0 = (i4 & 15) * 4;
    int oc  = (i4 >> 4) & 255;
    int tc  = i4 >> 12;
    int tap = tc >> 2, chunk = tc & 3;
    #pragma unroll
    for (int e = 0; e < 4; e++) {
        int ic = ic0 + e;
        float v = w2[(size_t)oc * 2304 + (chunk * 64 + ic) * 9 + tap];
        w216[(size_t)tc * 16384 + oc * 64 + ic] = __float2half(v);
    }
}

__global__ __launch_bounds__(256) void w13cvt_kernel(const float* __restrict__ w1,
                                                     const float* __restrict__ w3,
                                                     const float* __restrict__ wc) {
    int i = blockIdx.x * 256 + threadIdx.x;   // 0..16383
    {
        #pragma unroll
        for (int e = 0; e < 2; e++) {
            int idx = i * 2 + e;
            int ic = idx & 63, oc = (idx >> 6) & 255, ch = idx >> 14;
            w116[idx] = __float2half(w1[(size_t)oc * 128 + ch * 64 + ic]);
        }
    }
    {
        #pragma unroll
        for (int e = 0; e < 2; e++) {
            int idx = i * 2 + e;
            int ic = idx & 63, oc = (idx >> 6) & 127, ch = idx >> 13;
            w316[idx] = __float2half(w3[(size_t)oc * 256 + ch * 64 + ic]);
        }
    }
    if (i < 8192) {
        float v = wc[i];
        __nv_bfloat16 h = __float2bfloat16(v);
        wch[i] = h;
        wcl[i] = __float2bfloat16(v - __bfloat162float(h));
    }
}

// ---------------- convc: 1x1 64->128 via bf16 HMMA 3-pass, 128 px/CTA, fused stats ----------------
#define XCSTR  144
#define XCPART 18432
#define WCOFF  36864
#define WCPART 18432
#define SMEM_CCM (WCOFF + 2 * WCPART)
__global__ __launch_bounds__(256, 2) void convcm_kernel(const float* __restrict__ x,
                                                        const float* __restrict__ bc,
                                                        float* __restrict__ out) {
    extern __shared__ float smf[];
    char* smem = (char*)smf;
    int t = threadIdx.x, w = t >> 5, lane = t & 31;
    int g = lane >> 2, tg = lane & 3;
    int b  = blockIdx.x >> 9;
    int p0 = (blockIdx.x & 511) << 7;
    int ocb = (w & 1) * 64;
    int pxb = (w >> 1) * 32;

    {
        int icp = t & 31, pxg = t >> 5;
        const float* s0 = x + (((size_t)(b * CIN + icp * 2)) << 16) + p0 + pxg * 16;
        const float* s1 = s0 + HW;
        char* xb = smem + icp * 4;
        #pragma unroll
        for (int q = 0; q < 4; q++) {
            float4 u0 = ((const float4*)s0)[q];
            float4 u1 = ((const float4*)s1)[q];
            float v0[4] = {u0.x, u0.y, u0.z, u0.w};
            float v1[4] = {u1.x, u1.y, u1.z, u1.w};
            #pragma unroll
            for (int e = 0; e < 4; e++) {
                int px = pxg * 16 + q * 4 + e;
                __nv_bfloat16 h0 = __float2bfloat16(v0[e]);
                __nv_bfloat16 h1 = __float2bfloat16(v1[e]);
                __nv_bfloat16 l0 = __float2bfloat16(v0[e] - __bfloat162float(h0));
                __nv_bfloat16 l1 = __float2bfloat16(v1[e] - __bfloat162float(h1));
                *(unsigned*)(xb + px * XCSTR) =
                    PKU(__bfloat16_as_ushort(h0), __bfloat16_as_ushort(h1));
                *(unsigned*)(xb + XCPART + px * XCSTR) =
                    PKU(__bfloat16_as_ushort(l0), __bfloat16_as_ushort(l1));
            }
        }
    }
    {
        int part = t >> 7, oc = t & 127;
        const __nv_bfloat16* ws = (part ? wcl : wch) + oc * 64;
        const uint4* s = (const uint4*)ws;
        uint4* d = (uint4*)(smem + WCOFF + part * WCPART + oc * XCSTR);
        #pragma unroll
        for (int q = 0; q < 8; q++) d[q] = s[q];
    }
    __syncthreads();

    float acc[4][4][4];
    #pragma unroll
    for (int mt = 0; mt < 4; mt++)
        #pragma unroll
        for (int nt = 0; nt < 4; nt++)
            #pragma unroll
            for (int e = 0; e < 4; e++) acc[mt][nt][e] = 0.0f;

    #pragma unroll 1
    for (int pass = 0; pass < 3; pass++) {
        const char* A  = smem + WCOFF + ((pass == 1) ? WCPART : 0);
        const char* Bp = smem + ((pass == 2) ? XCPART : 0);
        #pragma unroll
        for (int k4 = 0; k4 < 4; k4++) {
            int kb = (k4 * 16 + 2 * tg) * 2;
            unsigned af[4][4];
            #pragma unroll
            for (int mt = 0; mt < 4; mt++) {
                const char* ar = A + (ocb + mt * 16 + g) * XCSTR + kb;
                af[mt][0] = *(const unsigned*)ar;
                af[mt][1] = *(const unsigned*)(ar + 8 * XCSTR);
                af[mt][2] = *(const unsigned*)(ar + 16);
                af[mt][3] = *(const unsigned*)(ar + 8 * XCSTR + 16);
            }
            #pragma unroll
            for (int nt = 0; nt < 4; nt++) {
                const char* br = Bp + (pxb + nt * 8 + g) * XCSTR + kb;
                unsigned b0 = *(const unsigned*)br;
                unsigned b1v = *(const unsigned*)(br + 16);
                #pragma unroll
                for (int mt = 0; mt < 4; mt++)
                    mma16816(acc[mt][nt], af[mt], b0, b1v);
            }
        }
    }

    float* dstb = out + (((size_t)(b * COUT)) << 16) + p0;
    #pragma unroll
    for (int mt = 0; mt < 4; mt++) {
        int oc_a = ocb + mt * 16 + g;
        int oc_b = oc_a + 8;
        float ba = bc[oc_a], bbv = bc[oc_b];
        float* da = dstb + (((size_t)oc_a) << 16) + pxb;
        float* db = dstb + (((size_t)oc_b) << 16) + pxb;
        float sa = 0.f, qa = 0.f, sb = 0.f, qb = 0.f;
        #pragma unroll
        for (int nt = 0; nt < 4; nt++) {
            int n0 = nt * 8 + tg * 2;
            float2 e0, e1;
            e0.x = fmaxf(acc[mt][nt][0] + ba, 0.f);
            e0.y = fmaxf(acc[mt][nt][1] + ba, 0.f);
            e1.x = fmaxf(acc[mt][nt][2] + bbv, 0.f);
            e1.y = fmaxf(acc[mt][nt][3] + bbv, 0.f);
            sa += e0.x + e0.y; qa += e0.x * e0.x + e0.y * e0.y;
            sb += e1.x + e1.y; qb += e1.x * e1.x + e1.y * e1.y;
            *(float2*)(da + n0) = e0;
            *(float2*)(db + n0) = e1;
        }
        quad_stats(sa, qa, tg, &d_sum0[oc_a], &d_sq0[oc_a]);
        quad_stats(sb, qb, tg, &d_sum0[oc_b], &d_sq0[oc_b]);
    }
}

__global__ __launch_bounds__(256) void bnapply_kernel(float* __restrict__ y) {
    int nth = gridDim.x * blockDim.x;
    int total = (B_ * COUT * HW) / 4;
    for (int i = blockIdx.x * blockDim.x + threadIdx.x; i < total; i += nth) {
        int c = (i >> 14) & 127;
        float4 v = reinterpret_cast<float4*>(y)[i];
        float a = d_a0[c], bb = d_b0[c];
        v.x = a * v.x + bb; v.y = a * v.y + bb;
        v.z = a * v.z + bb; v.w = a * v.w + bb;
        reinterpret_cast<float4*>(y)[i] = v;
    }
}

// ---------------- conv1: gather + 1x1 128->256, BN0 folded into X build ----------------
#define X1STR  144
#define X1PART 9216
#define X1BLK  18432
#define W1OFF  36864
#define SMEM_C1M (W1OFF + 36864)
__global__ __launch_bounds__(256, 1) void conv1m_kernel(const float* __restrict__ xraw,
                                                        const int* __restrict__ abi,
                                                        const float* __restrict__ b1) {
    extern __shared__ float smf[];
    char* smem = (char*)smf;
    uint32_t sbase = (uint32_t)__cvta_generic_to_shared(smem);
    int t = threadIdx.x, w = t >> 5, lane = t & 31;
    int g = lane >> 2, tg = lane & 3;
    int blk0 = blockIdx.x * 2;
    int mblk = w >> 2;
    int ocb  = (w & 3) * 64;

    float acc[4][8][4];
    #pragma unroll
    for (int mt = 0; mt < 4; mt++)
        #pragma unroll
        for (int nt = 0; nt < 8; nt++)
            #pragma unroll
            for (int e = 0; e < 4; e++) acc[mt][nt][e] = 0.0f;

    int brow = t >> 1, bsub = t & 1;
    int xblk = brow >> 6, xic = brow & 63;
    int n_  = abi[(blk0 + xblk) * 3 + 0];
    int bi_ = abi[(blk0 + xblk) * 3 + 1];
    int bj_ = abi[(blk0 + xblk) * 3 + 2];
    const float* gsrc0 = xraw + (((size_t)(n_ * COUT)) << 16) + bi_ * 2048 + bj_ * 8;

    for (int chunk = 0; chunk < 2; chunk++) {
        __syncthreads();
        {
            #pragma unroll
            for (int j = 0; j < 8; j++) {
                int idx = t + j * 256;
                int row = idx >> 3, q = idx & 7;
                const __half* gs = w116 + (size_t)chunk * 16384 + row * 64 + q * 8;
                uint32_t sd = sbase + W1OFF + row * X1STR + q * 16;
                cp_async16(sd, gs);
            }
            CP_COMMIT();
        }
        {
            int icg = chunk * 64 + xic;
            const float* src = gsrc0 + (((size_t)icg) << 16) + bsub * 4 * 256;
            float a0 = d_a0[icg], c0 = d_b0[icg];   // BN0 folded
            char* xb = smem + xblk * X1BLK + xic * 2;
            #pragma unroll
            for (int r4 = 0; r4 < 4; r4++) {
                float4 u  = *reinterpret_cast<const float4*>(src + r4 * 256);
                float4 v2 = *reinterpret_cast<const float4*>(src + r4 * 256 + 4);
                float vals[8] = {u.x, u.y, u.z, u.w, v2.x, v2.y, v2.z, v2.w};
                int px0 = bsub * 32 + r4 * 8;
                #pragma unroll
                for (int e = 0; e < 8; e++) {
                    float xv = a0 * vals[e] + c0;
                    __half h = __float2half(xv);
                    __half l = __float2half(xv - __half2float(h));
                    *(__half*)(xb + (px0 + e) * X1STR) = h;
                    *(__half*)(xb + X1PART + (px0 + e) * X1STR) = l;
                }
            }
        }
        CP_WAIT0();
        __syncthreads();

        const char* A  = smem + W1OFF;
        const char* Bh = smem + mblk * X1BLK;
        #pragma unroll
        for (int k4 = 0; k4 < 4; k4++) {
            int kb = (k4 * 16 + 2 * tg) * 2;
            unsigned af[4][4];
            #pragma unroll
            for (int mt = 0; mt < 4; mt++) {
                const char* ar = A + (ocb + mt * 16 + g) * X1STR + kb;
                af[mt][0] = *(const unsigned*)ar;
                af[mt][1] = *(const unsigned*)(ar + 8 * X1STR);
                af[mt][2] = *(const unsigned*)(ar + 16);
                af[mt][3] = *(const unsigned*)(ar + 8 * X1STR + 16);
            }
            #pragma unroll
            for (int nt = 0; nt < 8; nt++) {
                const char* br = Bh + (nt * 8 + g) * X1STR + kb;
                unsigned b0h = *(const unsigned*)br;
                unsigned b1h = *(const unsigned*)(br + 16);
                unsigned b0l = *(const unsigned*)(br + X1PART);
                unsigned b1l = *(const unsigned*)(br + X1PART + 16);
                #pragma unroll
                for (int mt = 0; mt < 4; mt++) {
                    mma16816h(acc[mt][nt], af[mt], b0h, b1h);
                    mma16816h(acc[mt][nt], af[mt], b0l, b1l);
                }
            }
        }
    }

    #pragma unroll
    for (int mt = 0; mt < 4; mt++) {
        int oc_a = ocb + mt * 16 + g;
        int oc_b = oc_a + 8;
        float ba = b1[oc_a], bbv = b1[oc_b];
        float* da = g1buf + ((size_t)(blk0 + mblk) * C2 + oc_a) * 64;
        float* db = g1buf + ((size_t)(blk0 + mblk) * C2 + oc_b) * 64;
        float sa = 0.f, qa = 0.f, sb = 0.f, qb = 0.f;
        #pragma unroll
        for (int nt = 0; nt < 8; nt++) {
            int n0 = nt * 8 + tg * 2;
            float2 e0, e1;
            e0.x = fmaxf(acc[mt][nt][0] + ba, 0.f);
            e0.y = fmaxf(acc[mt][nt][1] + ba, 0.f);
            e1.x = fmaxf(acc[mt][nt][2] + bbv, 0.f);
            e1.y = fmaxf(acc[mt][nt][3] + bbv, 0.f);
            sa += e0.x + e0.y; qa += e0.x * e0.x + e0.y * e0.y;
            sb += e1.x + e1.y; qb += e1.x * e1.x + e1.y * e1.y;
            *(float2*)(da + n0) = e0;
            *(float2*)(db + n0) = e1;
        }
        quad_stats(sa, qa, tg, &d_sum1[oc_a], &d_sq1[oc_a]);
        quad_stats(sb, qb, tg, &d_sum1[oc_b], &d_sq1[oc_b]);
    }
}

// ---------------- conv2: 3x3 via fp16 HMMA 1-PASS, padded-2D X, cp.async dbuf W ----------------
#define X2BLK  14400
#define W2OFF  28800
#define W2BUF  36864
#define SMEM_C2M (W2OFF + 2 * W2BUF)
__global__ __launch_bounds__(256, 1) void conv2m_kernel(const float* __restrict__ b2) {
    extern __shared__ float smf[];
    char* smem = (char*)smf;
    uint32_t sbase = (uint32_t)__cvta_generic_to_shared(smem);
    int t = threadIdx.x, w = t >> 5, lane = t & 31;
    int g = lane >> 2, tg = lane & 3;
    int blk0 = blockIdx.x * 2;
    int mblk = w >> 2;
    int ocb  = (w & 3) * 64;

    float acc[4][8][4];
    #pragma unroll
    for (int mt = 0; mt < 4; mt++)
        #pragma unroll
        for (int nt = 0; nt < 8; nt++)
            #pragma unroll
            for (int e = 0; e < 4; e++) acc[mt][nt][e] = 0.0f;

    // zero X once (halo stays zero)
    for (int i = t; i < W2OFF / 16; i += 256) ((uint4*)smem)[i] = make_uint4(0, 0, 0, 0);

    int xblk = t >> 7;
    int icp  = (t >> 2) & 31;
    int pxg  = t & 3;

    for (int chunk = 0; chunk < 4; chunk++) {
        __syncthreads();
        {
            int tc = chunk;
            #pragma unroll
            for (int j = 0; j < 8; j++) {
                int idx = t + j * 256;
                int row = idx >> 3, q = idx & 7;
                const __half* gs = w216 + (size_t)tc * 16384 + row * 64 + q * 8;
                uint32_t sd = sbase + W2OFF + row * X1STR + q * 16;
                cp_async16(sd, gs);
            }
            CP_COMMIT();
        }
        // X build: single fp16 plane
        {
            int ic0 = chunk * 64 + icp * 2;
            const float* s0 = g1buf + ((size_t)(blk0 + xblk) * C2 + ic0) * 64 + pxg * 16;
            const float* s1 = s0 + 64;
            float a0 = d_a1[ic0],     c0 = d_b1[ic0];
            float a1 = d_a1[ic0 + 1], c1 = d_b1[ic0 + 1];
            char* xb = smem + xblk * X2BLK + icp * 4;
            #pragma unroll
            for (int q = 0; q < 4; q++) {
                float4 u0 = ((const float4*)s0)[q];
                float4 u1 = ((const float4*)s1)[q];
                float v0[4] = {u0.x, u0.y, u0.z, u0.w};
                float v1[4] = {u1.x, u1.y, u1.z, u1.w};
                #pragma unroll
                for (int e = 0; e < 4; e++) {
                    int p = pxg * 16 + q * 4 + e;
                    int row = ((p >> 3) + 1) * 10 + (p & 7) + 1;
                    float x0 = a0 * v0[e] + c0;
                    float x1 = a1 * v1[e] + c1;
                    *(unsigned*)(xb + row * X1STR) =
                        PKU(__half_as_ushort(__float2half(x0)),
                            __half_as_ushort(__float2half(x1)));
                }
            }
        }

        for (int tap = 0; tap < 9; tap++) {
            CP_WAIT0();
            __syncthreads();
            int buf = tap & 1;
            if (tap < 8) {
                int tc = (tap + 1) * 4 + chunk;
                int ob = buf ^ 1;
                #pragma unroll
                for (int j = 0; j < 8; j++) {
                    int idx = t + j * 256;
                    int row = idx >> 3, q = idx & 7;
                    const __half* gs = w216 + (size_t)tc * 16384 + row * 64 + q * 8;
                    uint32_t sd = sbase + W2OFF + ob * W2BUF + row * X1STR + q * 16;
                    cp_async16(sd, gs);
                }
                CP_COMMIT();
            }

            int dr = tap / 3, dc = tap % 3;
            int rowc = dr * 10 + dc + g;
            const char* A  = smem + W2OFF + buf * W2BUF;
            const char* Bh = smem + mblk * X2BLK;
            #pragma unroll
            for (int k4 = 0; k4 < 4; k4++) {
                int kb = (k4 * 16 + 2 * tg) * 2;
                unsigned af[4][4];
                #pragma unroll
                for (int mt = 0; mt < 4; mt++) {
                    const char* ar = A + (ocb + mt * 16 + g) * X1STR + kb;
                    af[mt][0] = *(const unsigned*)ar;
                    af[mt][1] = *(const unsigned*)(ar + 8 * X1STR);
                    af[mt][2] = *(const unsigned*)(ar + 16);
                    af[mt][3] = *(const unsigned*)(ar + 8 * X1STR + 16);
                }
                #pragma unroll
                for (int nt = 0; nt < 8; nt++) {
                    const char* br = Bh + (rowc + nt * 10) * X1STR + kb;
                    unsigned b0h = *(const unsigned*)br;
                    unsigned b1h = *(const unsigned*)(br + 16);
                    #pragma unroll
                    for (int mt = 0; mt < 4; mt++)
                        mma16816h(acc[mt][nt], af[mt], b0h, b1h);
                }
            }
        }
    }

    #pragma unroll
    for (int mt = 0; mt < 4; mt++) {
        int oc_a = ocb + mt * 16 + g;
        int oc_b = oc_a + 8;
        float ba = b2[oc_a], bbv = b2[oc_b];
        float* da = g2buf + ((size_t)(blk0 + mblk) * C2 + oc_a) * 64;
        float* db = g2buf + ((size_t)(blk0 + mblk) * C2 + oc_b) * 64;
        float sa = 0.f, qa = 0.f, sb = 0.f, qb = 0.f;
        #pragma unroll
        for (int nt = 0; nt < 8; nt++) {
            int n0 = nt * 8 + tg * 2;
            float2 e0, e1;
            e0.x = fmaxf(acc[mt][nt][0] + ba, 0.f);
            e0.y = fmaxf(acc[mt][nt][1] + ba, 0.f);
            e1.x = fmaxf(acc[mt][nt][2] + bbv, 0.f);
            e1.y = fmaxf(acc[mt][nt][3] + bbv, 0.f);
            sa += e0.x + e0.y; qa += e0.x * e0.x + e0.y * e0.y;
            sb += e1.x + e1.y; qb += e1.x * e1.x + e1.y * e1.y;
            *(float2*)(da + n0) = e0;
            *(float2*)(db + n0) = e1;
        }
        quad_stats(sa, qa, tg, &d_sum2[oc_a], &d_sq2[oc_a]);
        quad_stats(sb, qb, tg, &d_sum2[oc_b], &d_sq2[oc_b]);
    }
}

// ---------------- conv3: 1x1 256->128 via fp16 HMMA 2-pass, 4 blocks/CTA, cp.async W ----------------
#define X3BLK  18432
#define W3OFF  73728
#define SMEM_C3M (W3OFF + 18432)
__global__ __launch_bounds__(256, 1) void conv3m_kernel(const float* __restrict__ b3) {
    extern __shared__ float smf[];
    char* smem = (char*)smf;
    uint32_t sbase = (uint32_t)__cvta_generic_to_shared(smem);
    int t = threadIdx.x, w = t >> 5, lane = t & 31;
    int g = lane >> 2, tg = lane & 3;
    int blk0 = blockIdx.x * 4;
    int mblk = w >> 1;
    int ocb  = (w & 1) * 64;

    float acc[4][8][4];
    #pragma unroll
    for (int mt = 0; mt < 4; mt++)
        #pragma unroll
        for (int nt = 0; nt < 8; nt++)
            #pragma unroll
            for (int e = 0; e < 4; e++) acc[mt][nt][e] = 0.0f;

    int xblk = t >> 6, xic = t & 63;

    for (int chunk = 0; chunk < 4; chunk++) {
        __syncthreads();
        {
            #pragma unroll
            for (int j = 0; j < 4; j++) {
                int idx = t + j * 256;
                int row = idx >> 3, q = idx & 7;
                const __half* gs = w316 + (size_t)chunk * 8192 + row * 64 + q * 8;
                uint32_t sd = sbase + W3OFF + row * X1STR + q * 16;
                cp_async16(sd, gs);
            }
            CP_COMMIT();
        }
        {
            int icg = chunk * 64 + xic;
            const float* src = g2buf + ((size_t)(blk0 + xblk) * C2 + icg) * 64;
            float a = d_a2[icg], bb = d_b2[icg];
            char* xb = smem + xblk * X3BLK + xic * 2;
            #pragma unroll
            for (int j = 0; j < 16; j++) {
                float4 v4 = ((const float4*)src)[j];
                float vals[4] = {v4.x, v4.y, v4.z, v4.w};
                #pragma unroll
                for (int e = 0; e < 4; e++) {
                    int px = j * 4 + e;
                    float xv = a * vals[e] + bb;
                    __half h = __float2half(xv);
                    __half l = __float2half(xv - __half2float(h));
                    *(__half*)(xb + px * X1STR) = h;
                    *(__half*)(xb + X1PART + px * X1STR) = l;
                }
            }
        }
        CP_WAIT0();
        __syncthreads();

        const char* A  = smem + W3OFF;
        const char* Bh = smem + mblk * X3BLK;
        #pragma unroll
        for (int k4 = 0; k4 < 4; k4++) {
            int kb = (k4 * 16 + 2 * tg) * 2;
            unsigned af[4][4];
            #pragma unroll
            for (int mt = 0; mt < 4; mt++) {
                const char* ar = A + (ocb + mt * 16 + g) * X1STR + kb;
                af[mt][0] = *(const unsigned*)ar;
                af[mt][1] = *(const unsigned*)(ar + 8 * X1STR);
                af[mt][2] = *(const unsigned*)(ar + 16);
                af[mt][3] = *(const unsigned*)(ar + 8 * X1STR + 16);
            }
            #pragma unroll
            for (int nt = 0; nt < 8; nt++) {
                const char* br = Bh + (nt * 8 + g) * X1STR + kb;
                unsigned b0h = *(const unsigned*)br;
                unsigned b1h = *(const unsigned*)(br + 16);
                unsigned b0l = *(const unsigned*)(br + X1PART);
                unsigned b1l = *(const unsigned*)(br + X1PART + 16);
                #pragma unroll
                for (int mt = 0; mt < 4; mt++) {
                    mma16816h(acc[mt][nt], af[mt], b0h, b1h);
                    mma16816h(acc[mt][nt], af[mt], b0l, b1l);
                }
            }
        }
    }

    #pragma unroll
    for (int mt = 0; mt < 4; mt++) {
        int oc_a = ocb + mt * 16 + g;
        int oc_b = oc_a + 8;
        float ba = b3[oc_a], bbv = b3[oc_b];
        float* da = g3buf + ((size_t)(blk0 + mblk) * COUT + oc_a) * 64;
        float* db = g3buf + ((size_t)(blk0 + mblk) * COUT + oc_b) * 64;
        float sa = 0.f, qa = 0.f, sb = 0.f, qb = 0.f;
        #pragma unroll
        for (int nt = 0; nt < 8; nt++) {
            int n0 = nt * 8 + tg * 2;
            float2 e0, e1;
            e0.x = fmaxf(acc[mt][nt][0] + ba, 0.f);
            e0.y = fmaxf(acc[mt][nt][1] + ba, 0.f);
            e1.x = fmaxf(acc[mt][nt][2] + bbv, 0.f);
            e1.y = fmaxf(acc[mt][nt][3] + bbv, 0.f);
            sa += e0.x + e0.y; qa += e0.x * e0.x + e0.y * e0.y;
            sb += e1.x + e1.y; qb += e1.x * e1.x + e1.y * e1.y;
            *(float2*)(da + n0) = e0;
            *(float2*)(db + n0) = e1;
        }
        quad_stats(sa, qa, tg, &d_sum3[oc_a], &d_sq3[oc_a]);
        quad_stats(sb, qb, tg, &d_sum3[oc_b], &d_sq3[oc_b]);
    }
}

// ---------------- scatter: BN3(g3) -> image ----------------
__global__ __launch_bounds__(256) void scatter_kernel(const int* __restrict__ abi,
                                                      float* __restrict__ out) {
    int blk = blockIdx.x;
    int n  = abi[blk * 3 + 0];
    int bi = abi[blk * 3 + 1];
    int bj = abi[blk * 3 + 2];
    const float* src = g3buf + (size_t)blk * COUT * 64;
    float* dst = out + (((size_t)(n * COUT)) << 16) + bi * 8 * 256 + bj * 8;
    for (int i = threadIdx.x; i < 2048; i += 256) {
        int c = i >> 4, q = i & 15;
        int r = q >> 1, c4 = (q & 1) * 4;
        float4 v = *reinterpret_cast<const float4*>(src + c * 64 + q * 4);
        float a = d_a3[c], bb = d_b3[c];
        v.x = a * v.x + bb; v.y = a * v.y + bb;
        v.z = a * v.z + bb; v.w = a * v.w + bb;
        *reinterpret_cast<float4*>(dst + (((size_t)c) << 16) + r * 256 + c4) = v;
    }
}

// ---------------- launch ----------------
extern "C" void kernel_launch(void* const* d_in, const int* in_sizes, int n_in,
                              void* d_out, int out_size) {
    const float* x    = (const float*)d_in[0];
    const int*   abi  = (const int*)  d_in[1];
    const float* w_c  = (const float*)d_in[2];
    const float* b_c  = (const float*)d_in[3];
    const float* gm_c = (const float*)d_in[4];
    const float* be_c = (const float*)d_in[5];
    const float* w1   = (const float*)d_in[6];
    const float* b1   = (const float*)d_in[7];
    const float* gm1  = (const float*)d_in[8];
    const float* be1  = (const float*)d_in[9];
    const float* w2   = (const float*)d_in[10];
    const float* b2   = (const float*)d_in[11];
    const float* gm2  = (const float*)d_in[12];
    const float* be2  = (const float*)d_in[13];
    const float* w3   = (const float*)d_in[14];
    const float* b3   = (const float*)d_in[15];
    const float* gm3  = (const float*)d_in[16];
    const float* be3  = (const float*)d_in[17];
    float* out = (float*)d_out;

    static cudaStream_t s2 = nullptr;
    static cudaEvent_t evf = nullptr, evj = nullptr;
    if (s2 == nullptr) {
        cudaStreamCreateWithFlags(&s2, cudaStreamNonBlocking);
        cudaEventCreateWithFlags(&evf, cudaEventDisableTiming);
        cudaEventCreateWithFlags(&evj, cudaEventDisableTiming);
    }

    cudaFuncSetAttribute(convcm_kernel, cudaFuncAttributeMaxDynamicSharedMemorySize, SMEM_CCM);
    cudaFuncSetAttribute(conv1m_kernel, cudaFuncAttributeMaxDynamicSharedMemorySize, SMEM_C1M);
    cudaFuncSetAttribute(conv2m_kernel, cudaFuncAttributeMaxDynamicSharedMemorySize, SMEM_C2M);
    cudaFuncSetAttribute(conv3m_kernel, cudaFuncAttributeMaxDynamicSharedMemorySize, SMEM_C3M);

    zero_stats_kernel<<<1, 256>>>();
    w2cvt_kernel<<<576, 256>>>(w2);
    w13cvt_kernel<<<64, 256>>>(w1, w3, w_c);

    convcm_kernel<<<4096, 256, SMEM_CCM>>>(x, b_c, out);
    finalize_kernel<<<1, 256>>>(0, gm_c, be_c, 1.0 / 524288.0);

    // conv1 reads the raw (pre-BN0) image and folds BN0 into its X build
    conv1m_kernel<<<2048, 256, SMEM_C1M>>>(out, abi, b1);

    // fork: BN0-apply the full image on a side stream (overlaps conv2/conv3)
    cudaEventRecord(evf, 0);
    cudaStreamWaitEvent(s2, evf, 0);
    bnapply_kernel<<<16384, 256, 0, s2>>>(out);
    cudaEventRecord(evj, s2);

    finalize_kernel<<<1, 256>>>(1, gm1, be1, 1.0 / 262144.0);

    conv2m_kernel<<<2048, 256, SMEM_C2M>>>(b2);
    finalize_kernel<<<1, 256>>>(2, gm2, be2, 1.0 / 262144.0);

    conv3m_kernel<<<1024, 256, SMEM_C3M>>>(b3);
    finalize_kernel<<<1, 256>>>(3, gm3, be3, 1.0 / 262144.0);

    // join before scatter overwrites block regions of out
    cudaStreamWaitEvent(0, evj, 0);
    scatter_kernel<<<4096, 256>>>(abi, out);
}

// round 17
// speedup vs baseline: 1.6165x; 1.0476x over previous
#include <cuda_runtime.h>
#include <cuda_bf16.h>
#include <cuda_fp16.h>
#include <math.h>
#include <stdint.h>

#define B_    8
#define CIN   64
#define COUT  128
#define C2    256
#define HW    65536
#define NBLK  4096
#define EPSV  1e-5f

// ---------------- scratch ----------------
__device__ float g1buf[(size_t)NBLK * C2 * 64];
__device__ float g2buf[(size_t)NBLK * C2 * 64];
__device__ float g3buf[(size_t)NBLK * COUT * 64];

// fp16 weights (block convs), bf16 hi/lo for convc
__device__ __half w216[36 * 16384];  // [tap*4+chunk][oc 256][ic 64]
__device__ __half w116[2 * 16384];   // [chunk2][oc 256][ic 64]
__device__ __half w316[4 * 8192];    // [chunk4][oc 128][ic 64]
__device__ __nv_bfloat16 wch[8192];  // [oc 128][ic 64]
__device__ __nv_bfloat16 wcl[8192];

__device__ double d_sum0[COUT], d_sq0[COUT];
__device__ double d_sum1[C2],   d_sq1[C2];
__device__ double d_sum2[C2],   d_sq2[C2];
__device__ double d_sum3[COUT], d_sq3[COUT];
__device__ float  d_a0[COUT], d_b0[COUT];
__device__ float  d_a1[C2],   d_b1[C2];
__device__ float  d_a2[C2],   d_b2[C2];
__device__ float  d_a3[COUT], d_b3[COUT];

#define PKU(x, y) ((unsigned)(x) | ((unsigned)(y) << 16))

// ---------------- MMA helpers ----------------
__device__ __forceinline__ void mma16816(float* d, const unsigned* a, unsigned b0, unsigned b1) {
    asm volatile(
        "mma.sync.aligned.m16n8k16.row.col.f32.bf16.bf16.f32 "
        "{%0,%1,%2,%3}, {%4,%5,%6,%7}, {%8,%9}, {%0,%1,%2,%3};"
        : "+f"(d[0]), "+f"(d[1]), "+f"(d[2]), "+f"(d[3])
        : "r"(a[0]), "r"(a[1]), "r"(a[2]), "r"(a[3]), "r"(b0), "r"(b1));
}
__device__ __forceinline__ void mma16816h(float* d, const unsigned* a, unsigned b0, unsigned b1) {
    asm volatile(
        "mma.sync.aligned.m16n8k16.row.col.f32.f16.f16.f32 "
        "{%0,%1,%2,%3}, {%4,%5,%6,%7}, {%8,%9}, {%0,%1,%2,%3};"
        : "+f"(d[0]), "+f"(d[1]), "+f"(d[2]), "+f"(d[3])
        : "r"(a[0]), "r"(a[1]), "r"(a[2]), "r"(a[3]), "r"(b0), "r"(b1));
}

__device__ __forceinline__ void cp_async16(uint32_t sdst, const void* gsrc) {
    asm volatile("cp.async.cg.shared.global [%0], [%1], 16;" :: "r"(sdst), "l"(gsrc));
}
#define CP_COMMIT() asm volatile("cp.async.commit_group;" ::: "memory")
#define CP_WAIT0()  asm volatile("cp.async.wait_group 0;" ::: "memory")

__device__ __forceinline__ void quad_stats(float s, float s2, int tg,
                                           double* gsum, double* gsq) {
    s  += __shfl_xor_sync(0xffffffffu, s, 1);
    s  += __shfl_xor_sync(0xffffffffu, s, 2);
    s2 += __shfl_xor_sync(0xffffffffu, s2, 1);
    s2 += __shfl_xor_sync(0xffffffffu, s2, 2);
    if (tg == 0) { atomicAdd(gsum, (double)s); atomicAdd(gsq, (double)s2); }
}

// ---------------- utility ----------------
__global__ void zero_stats_kernel() {
    int t = threadIdx.x;
    if (t < COUT) { d_sum0[t] = 0.0; d_sq0[t] = 0.0; d_sum3[t] = 0.0; d_sq3[t] = 0.0; }
    d_sum1[t] = 0.0; d_sq1[t] = 0.0; d_sum2[t] = 0.0; d_sq2[t] = 0.0;
}

__global__ void finalize_kernel(int stage, const float* __restrict__ gamma,
                                const float* __restrict__ beta, double invN) {
    int t = threadIdx.x;
    const double *sum, *sq; float *a, *bsh; int C;
    if (stage == 0)      { sum = d_sum0; sq = d_sq0; a = d_a0; bsh = d_b0; C = COUT; }
    else if (stage == 1) { sum = d_sum1; sq = d_sq1; a = d_a1; bsh = d_b1; C = C2; }
    else if (stage == 2) { sum = d_sum2; sq = d_sq2; a = d_a2; bsh = d_b2; C = C2; }
    else                 { sum = d_sum3; sq = d_sq3; a = d_a3; bsh = d_b3; C = COUT; }
    if (t < C) {
        double mean = sum[t] * invN;
        double var  = sq[t] * invN - mean * mean;
        float v = fmaxf((float)var, 0.0f);
        float av = gamma[t] * rsqrtf(v + EPSV);
        a[t] = av;
        bsh[t] = beta[t] - av * (float)mean;
    }
}

// ---------------- weight converts ----------------
__global__ __launch_bounds__(256) void w2cvt_kernel(const float* __restrict__ w2) {
    int i4 = blockIdx.x * 256 + threadIdx.x;
    int ic0 = (i4 & 15) * 4;
    int oc  = (i4 >> 4) & 255;
    int tc  = i4 >> 12;
    int tap = tc >> 2, chunk = tc & 3;
    #pragma unroll
    for (int e = 0; e < 4; e++) {
        int ic = ic0 + e;
        float v = w2[(size_t)oc * 2304 + (chunk * 64 + ic) * 9 + tap];
        w216[(size_t)tc * 16384 + oc * 64 + ic] = __float2half(v);
    }
}

__global__ __launch_bounds__(256) void w13cvt_kernel(const float* __restrict__ w1,
                                                     const float* __restrict__ w3,
                                                     const float* __restrict__ wc) {
    int i = blockIdx.x * 256 + threadIdx.x;   // 0..16383
    {
        #pragma unroll
        for (int e = 0; e < 2; e++) {
            int idx = i * 2 + e;
            int ic = idx & 63, oc = (idx >> 6) & 255, ch = idx >> 14;
            w116[idx] = __float2half(w1[(size_t)oc * 128 + ch * 64 + ic]);
        }
    }
    {
        #pragma unroll
        for (int e = 0; e < 2; e++) {
            int idx = i * 2 + e;
            int ic = idx & 63, oc = (idx >> 6) & 127, ch = idx >> 13;
            w316[idx] = __float2half(w3[(size_t)oc * 256 + ch * 64 + ic]);
        }
    }
    if (i < 8192) {
        float v = wc[i];
        __nv_bfloat16 h = __float2bfloat16(v);
        wch[i] = h;
        wcl[i] = __float2bfloat16(v - __bfloat162float(h));
    }
}

// ---------------- convc: 1x1 64->128 via bf16 HMMA 3-pass, 128 px/CTA, fused stats ----------------
#define XCSTR  144
#define XCPART 18432
#define WCOFF  36864
#define WCPART 18432
#define SMEM_CCM (WCOFF + 2 * WCPART)
__global__ __launch_bounds__(256, 2) void convcm_kernel(const float* __restrict__ x,
                                                        const float* __restrict__ bc,
                                                        float* __restrict__ out) {
    extern __shared__ float smf[];
    char* smem = (char*)smf;
    int t = threadIdx.x, w = t >> 5, lane = t & 31;
    int g = lane >> 2, tg = lane & 3;
    int b  = blockIdx.x >> 9;
    int p0 = (blockIdx.x & 511) << 7;
    int ocb = (w & 1) * 64;
    int pxb = (w >> 1) * 32;

    {
        int icp = t & 31, pxg = t >> 5;
        const float* s0 = x + (((size_t)(b * CIN + icp * 2)) << 16) + p0 + pxg * 16;
        const float* s1 = s0 + HW;
        char* xb = smem + icp * 4;
        #pragma unroll
        for (int q = 0; q < 4; q++) {
            float4 u0 = ((const float4*)s0)[q];
            float4 u1 = ((const float4*)s1)[q];
            float v0[4] = {u0.x, u0.y, u0.z, u0.w};
            float v1[4] = {u1.x, u1.y, u1.z, u1.w};
            #pragma unroll
            for (int e = 0; e < 4; e++) {
                int px = pxg * 16 + q * 4 + e;
                __nv_bfloat16 h0 = __float2bfloat16(v0[e]);
                __nv_bfloat16 h1 = __float2bfloat16(v1[e]);
                __nv_bfloat16 l0 = __float2bfloat16(v0[e] - __bfloat162float(h0));
                __nv_bfloat16 l1 = __float2bfloat16(v1[e] - __bfloat162float(h1));
                *(unsigned*)(xb + px * XCSTR) =
                    PKU(__bfloat16_as_ushort(h0), __bfloat16_as_ushort(h1));
                *(unsigned*)(xb + XCPART + px * XCSTR) =
                    PKU(__bfloat16_as_ushort(l0), __bfloat16_as_ushort(l1));
            }
        }
    }
    {
        int part = t >> 7, oc = t & 127;
        const __nv_bfloat16* ws = (part ? wcl : wch) + oc * 64;
        const uint4* s = (const uint4*)ws;
        uint4* d = (uint4*)(smem + WCOFF + part * WCPART + oc * XCSTR);
        #pragma unroll
        for (int q = 0; q < 8; q++) d[q] = s[q];
    }
    __syncthreads();

    float acc[4][4][4];
    #pragma unroll
    for (int mt = 0; mt < 4; mt++)
        #pragma unroll
        for (int nt = 0; nt < 4; nt++)
            #pragma unroll
            for (int e = 0; e < 4; e++) acc[mt][nt][e] = 0.0f;

    #pragma unroll 1
    for (int pass = 0; pass < 3; pass++) {
        const char* A  = smem + WCOFF + ((pass == 1) ? WCPART : 0);
        const char* Bp = smem + ((pass == 2) ? XCPART : 0);
        #pragma unroll
        for (int k4 = 0; k4 < 4; k4++) {
            int kb = (k4 * 16 + 2 * tg) * 2;
            unsigned af[4][4];
            #pragma unroll
            for (int mt = 0; mt < 4; mt++) {
                const char* ar = A + (ocb + mt * 16 + g) * XCSTR + kb;
                af[mt][0] = *(const unsigned*)ar;
                af[mt][1] = *(const unsigned*)(ar + 8 * XCSTR);
                af[mt][2] = *(const unsigned*)(ar + 16);
                af[mt][3] = *(const unsigned*)(ar + 8 * XCSTR + 16);
            }
            #pragma unroll
            for (int nt = 0; nt < 4; nt++) {
                const char* br = Bp + (pxb + nt * 8 + g) * XCSTR + kb;
                unsigned b0 = *(const unsigned*)br;
                unsigned b1v = *(const unsigned*)(br + 16);
                #pragma unroll
                for (int mt = 0; mt < 4; mt++)
                    mma16816(acc[mt][nt], af[mt], b0, b1v);
            }
        }
    }

    float* dstb = out + (((size_t)(b * COUT)) << 16) + p0;
    #pragma unroll
    for (int mt = 0; mt < 4; mt++) {
        int oc_a = ocb + mt * 16 + g;
        int oc_b = oc_a + 8;
        float ba = bc[oc_a], bbv = bc[oc_b];
        float* da = dstb + (((size_t)oc_a) << 16) + pxb;
        float* db = dstb + (((size_t)oc_b) << 16) + pxb;
        float sa = 0.f, qa = 0.f, sb = 0.f, qb = 0.f;
        #pragma unroll
        for (int nt = 0; nt < 4; nt++) {
            int n0 = nt * 8 + tg * 2;
            float2 e0, e1;
            e0.x = fmaxf(acc[mt][nt][0] + ba, 0.f);
            e0.y = fmaxf(acc[mt][nt][1] + ba, 0.f);
            e1.x = fmaxf(acc[mt][nt][2] + bbv, 0.f);
            e1.y = fmaxf(acc[mt][nt][3] + bbv, 0.f);
            sa += e0.x + e0.y; qa += e0.x * e0.x + e0.y * e0.y;
            sb += e1.x + e1.y; qb += e1.x * e1.x + e1.y * e1.y;
            *(float2*)(da + n0) = e0;
            *(float2*)(db + n0) = e1;
        }
        quad_stats(sa, qa, tg, &d_sum0[oc_a], &d_sq0[oc_a]);
        quad_stats(sb, qb, tg, &d_sum0[oc_b], &d_sq0[oc_b]);
    }
}

__global__ __launch_bounds__(256) void bnapply_kernel(float* __restrict__ y) {
    int nth = gridDim.x * blockDim.x;
    int total = (B_ * COUT * HW) / 4;
    for (int i = blockIdx.x * blockDim.x + threadIdx.x; i < total; i += nth) {
        int c = (i >> 14) & 127;
        float4 v = reinterpret_cast<float4*>(y)[i];
        float a = d_a0[c], bb = d_b0[c];
        v.x = a * v.x + bb; v.y = a * v.y + bb;
        v.z = a * v.z + bb; v.w = a * v.w + bb;
        reinterpret_cast<float4*>(y)[i] = v;
    }
}

// ---------------- conv1: gather + 1x1 128->256, fp16 1-PASS, BN0 folded ----------------
#define X1STR  144
#define X1BLK  9216
#define W1OFF  18432
#define SMEM_C1M (W1OFF + 36864)
__global__ __launch_bounds__(256, 1) void conv1m_kernel(const float* __restrict__ xraw,
                                                        const int* __restrict__ abi,
                                                        const float* __restrict__ b1) {
    extern __shared__ float smf[];
    char* smem = (char*)smf;
    uint32_t sbase = (uint32_t)__cvta_generic_to_shared(smem);
    int t = threadIdx.x, w = t >> 5, lane = t & 31;
    int g = lane >> 2, tg = lane & 3;
    int blk0 = blockIdx.x * 2;
    int mblk = w >> 2;
    int ocb  = (w & 3) * 64;

    float acc[4][8][4];
    #pragma unroll
    for (int mt = 0; mt < 4; mt++)
        #pragma unroll
        for (int nt = 0; nt < 8; nt++)
            #pragma unroll
            for (int e = 0; e < 4; e++) acc[mt][nt][e] = 0.0f;

    int brow = t >> 1, bsub = t & 1;
    int xblk = brow >> 6, xic = brow & 63;
    int n_  = abi[(blk0 + xblk) * 3 + 0];
    int bi_ = abi[(blk0 + xblk) * 3 + 1];
    int bj_ = abi[(blk0 + xblk) * 3 + 2];
    const float* gsrc0 = xraw + (((size_t)(n_ * COUT)) << 16) + bi_ * 2048 + bj_ * 8;

    for (int chunk = 0; chunk < 2; chunk++) {
        __syncthreads();
        {
            #pragma unroll
            for (int j = 0; j < 8; j++) {
                int idx = t + j * 256;
                int row = idx >> 3, q = idx & 7;
                const __half* gs = w116 + (size_t)chunk * 16384 + row * 64 + q * 8;
                uint32_t sd = sbase + W1OFF + row * X1STR + q * 16;
                cp_async16(sd, gs);
            }
            CP_COMMIT();
        }
        {
            int icg = chunk * 64 + xic;
            const float* src = gsrc0 + (((size_t)icg) << 16) + bsub * 4 * 256;
            float a0 = d_a0[icg], c0 = d_b0[icg];   // BN0 folded
            char* xb = smem + xblk * X1BLK + xic * 2;
            #pragma unroll
            for (int r4 = 0; r4 < 4; r4++) {
                float4 u  = *reinterpret_cast<const float4*>(src + r4 * 256);
                float4 v2 = *reinterpret_cast<const float4*>(src + r4 * 256 + 4);
                float vals[8] = {u.x, u.y, u.z, u.w, v2.x, v2.y, v2.z, v2.w};
                int px0 = bsub * 32 + r4 * 8;
                #pragma unroll
                for (int e = 0; e < 8; e++) {
                    float xv = a0 * vals[e] + c0;
                    *(__half*)(xb + (px0 + e) * X1STR) = __float2half(xv);
                }
            }
        }
        CP_WAIT0();
        __syncthreads();

        const char* A  = smem + W1OFF;
        const char* Bh = smem + mblk * X1BLK;
        #pragma unroll
        for (int k4 = 0; k4 < 4; k4++) {
            int kb = (k4 * 16 + 2 * tg) * 2;
            unsigned af[4][4];
            #pragma unroll
            for (int mt = 0; mt < 4; mt++) {
                const char* ar = A + (ocb + mt * 16 + g) * X1STR + kb;
                af[mt][0] = *(const unsigned*)ar;
                af[mt][1] = *(const unsigned*)(ar + 8 * X1STR);
                af[mt][2] = *(const unsigned*)(ar + 16);
                af[mt][3] = *(const unsigned*)(ar + 8 * X1STR + 16);
            }
            #pragma unroll
            for (int nt = 0; nt < 8; nt++) {
                const char* br = Bh + (nt * 8 + g) * X1STR + kb;
                unsigned b0h = *(const unsigned*)br;
                unsigned b1h = *(const unsigned*)(br + 16);
                #pragma unroll
                for (int mt = 0; mt < 4; mt++)
                    mma16816h(acc[mt][nt], af[mt], b0h, b1h);
            }
        }
    }

    #pragma unroll
    for (int mt = 0; mt < 4; mt++) {
        int oc_a = ocb + mt * 16 + g;
        int oc_b = oc_a + 8;
        float ba = b1[oc_a], bbv = b1[oc_b];
        float* da = g1buf + ((size_t)(blk0 + mblk) * C2 + oc_a) * 64;
        float* db = g1buf + ((size_t)(blk0 + mblk) * C2 + oc_b) * 64;
        float sa = 0.f, qa = 0.f, sb = 0.f, qb = 0.f;
        #pragma unroll
        for (int nt = 0; nt < 8; nt++) {
            int n0 = nt * 8 + tg * 2;
            float2 e0, e1;
            e0.x = fmaxf(acc[mt][nt][0] + ba, 0.f);
            e0.y = fmaxf(acc[mt][nt][1] + ba, 0.f);
            e1.x = fmaxf(acc[mt][nt][2] + bbv, 0.f);
            e1.y = fmaxf(acc[mt][nt][3] + bbv, 0.f);
            sa += e0.x + e0.y; qa += e0.x * e0.x + e0.y * e0.y;
            sb += e1.x + e1.y; qb += e1.x * e1.x + e1.y * e1.y;
            *(float2*)(da + n0) = e0;
            *(float2*)(db + n0) = e1;
        }
        quad_stats(sa, qa, tg, &d_sum1[oc_a], &d_sq1[oc_a]);
        quad_stats(sb, qb, tg, &d_sum1[oc_b], &d_sq1[oc_b]);
    }
}

// ---------------- conv2: 3x3 via fp16 HMMA 1-PASS, padded-2D X, cp.async dbuf W ----------------
#define X2BLK  14400
#define W2OFF  28800
#define W2BUF  36864
#define SMEM_C2M (W2OFF + 2 * W2BUF)
__global__ __launch_bounds__(256, 1) void conv2m_kernel(const float* __restrict__ b2) {
    extern __shared__ float smf[];
    char* smem = (char*)smf;
    uint32_t sbase = (uint32_t)__cvta_generic_to_shared(smem);
    int t = threadIdx.x, w = t >> 5, lane = t & 31;
    int g = lane >> 2, tg = lane & 3;
    int blk0 = blockIdx.x * 2;
    int mblk = w >> 2;
    int ocb  = (w & 3) * 64;

    float acc[4][8][4];
    #pragma unroll
    for (int mt = 0; mt < 4; mt++)
        #pragma unroll
        for (int nt = 0; nt < 8; nt++)
            #pragma unroll
            for (int e = 0; e < 4; e++) acc[mt][nt][e] = 0.0f;

    for (int i = t; i < W2OFF / 16; i += 256) ((uint4*)smem)[i] = make_uint4(0, 0, 0, 0);

    int xblk = t >> 7;
    int icp  = (t >> 2) & 31;
    int pxg  = t & 3;

    for (int chunk = 0; chunk < 4; chunk++) {
        __syncthreads();
        {
            int tc = chunk;
            #pragma unroll
            for (int j = 0; j < 8; j++) {
                int idx = t + j * 256;
                int row = idx >> 3, q = idx & 7;
                const __half* gs = w216 + (size_t)tc * 16384 + row * 64 + q * 8;
                uint32_t sd = sbase + W2OFF + row * X1STR + q * 16;
                cp_async16(sd, gs);
            }
            CP_COMMIT();
        }
        {
            int ic0 = chunk * 64 + icp * 2;
            const float* s0 = g1buf + ((size_t)(blk0 + xblk) * C2 + ic0) * 64 + pxg * 16;
            const float* s1 = s0 + 64;
            float a0 = d_a1[ic0],     c0 = d_b1[ic0];
            float a1 = d_a1[ic0 + 1], c1 = d_b1[ic0 + 1];
            char* xb = smem + xblk * X2BLK + icp * 4;
            #pragma unroll
            for (int q = 0; q < 4; q++) {
                float4 u0 = ((const float4*)s0)[q];
                float4 u1 = ((const float4*)s1)[q];
                float v0[4] = {u0.x, u0.y, u0.z, u0.w};
                float v1[4] = {u1.x, u1.y, u1.z, u1.w};
                #pragma unroll
                for (int e = 0; e < 4; e++) {
                    int p = pxg * 16 + q * 4 + e;
                    int row = ((p >> 3) + 1) * 10 + (p & 7) + 1;
                    float x0 = a0 * v0[e] + c0;
                    float x1 = a1 * v1[e] + c1;
                    *(unsigned*)(xb + row * X1STR) =
                        PKU(__half_as_ushort(__float2half(x0)),
                            __half_as_ushort(__float2half(x1)));
                }
            }
        }

        for (int tap = 0; tap < 9; tap++) {
            CP_WAIT0();
            __syncthreads();
            int buf = tap & 1;
            if (tap < 8) {
                int tc = (tap + 1) * 4 + chunk;
                int ob = buf ^ 1;
                #pragma unroll
                for (int j = 0; j < 8; j++) {
                    int idx = t + j * 256;
                    int row = idx >> 3, q = idx & 7;
                    const __half* gs = w216 + (size_t)tc * 16384 + row * 64 + q * 8;
                    uint32_t sd = sbase + W2OFF + ob * W2BUF + row * X1STR + q * 16;
                    cp_async16(sd, gs);
                }
                CP_COMMIT();
            }

            int dr = tap / 3, dc = tap % 3;
            int rowc = dr * 10 + dc + g;
            const char* A  = smem + W2OFF + buf * W2BUF;
            const char* Bh = smem + mblk * X2BLK;
            #pragma unroll
            for (int k4 = 0; k4 < 4; k4++) {
                int kb = (k4 * 16 + 2 * tg) * 2;
                unsigned af[4][4];
                #pragma unroll
                for (int mt = 0; mt < 4; mt++) {
                    const char* ar = A + (ocb + mt * 16 + g) * X1STR + kb;
                    af[mt][0] = *(const unsigned*)ar;
                    af[mt][1] = *(const unsigned*)(ar + 8 * X1STR);
                    af[mt][2] = *(const unsigned*)(ar + 16);
                    af[mt][3] = *(const unsigned*)(ar + 8 * X1STR + 16);
                }
                #pragma unroll
                for (int nt = 0; nt < 8; nt++) {
                    const char* br = Bh + (rowc + nt * 10) * X1STR + kb;
                    unsigned b0h = *(const unsigned*)br;
                    unsigned b1h = *(const unsigned*)(br + 16);
                    #pragma unroll
                    for (int mt = 0; mt < 4; mt++)
                        mma16816h(acc[mt][nt], af[mt], b0h, b1h);
                }
            }
        }
    }

    #pragma unroll
    for (int mt = 0; mt < 4; mt++) {
        int oc_a = ocb + mt * 16 + g;
        int oc_b = oc_a + 8;
        float ba = b2[oc_a], bbv = b2[oc_b];
        float* da = g2buf + ((size_t)(blk0 + mblk) * C2 + oc_a) * 64;
        float* db = g2buf + ((size_t)(blk0 + mblk) * C2 + oc_b) * 64;
        float sa = 0.f, qa = 0.f, sb = 0.f, qb = 0.f;
        #pragma unroll
        for (int nt = 0; nt < 8; nt++) {
            int n0 = nt * 8 + tg * 2;
            float2 e0, e1;
            e0.x = fmaxf(acc[mt][nt][0] + ba, 0.f);
            e0.y = fmaxf(acc[mt][nt][1] + ba, 0.f);
            e1.x = fmaxf(acc[mt][nt][2] + bbv, 0.f);
            e1.y = fmaxf(acc[mt][nt][3] + bbv, 0.f);
            sa += e0.x + e0.y; qa += e0.x * e0.x + e0.y * e0.y;
            sb += e1.x + e1.y; qb += e1.x * e1.x + e1.y * e1.y;
            *(float2*)(da + n0) = e0;
            *(float2*)(db + n0) = e1;
        }
        quad_stats(sa, qa, tg, &d_sum2[oc_a], &d_sq2[oc_a]);
        quad_stats(sb, qb, tg, &d_sum2[oc_b], &d_sq2[oc_b]);
    }
}

// ---------------- conv3: 1x1 256->128 via fp16 HMMA 1-PASS, 4 blocks/CTA ----------------
#define X3BLK  9216
#define W3OFF  36864
#define SMEM_C3M (W3OFF + 18432)
__global__ __launch_bounds__(256, 1) void conv3m_kernel(const float* __restrict__ b3) {
    extern __shared__ float smf[];
    char* smem = (char*)smf;
    uint32_t sbase = (uint32_t)__cvta_generic_to_shared(smem);
    int t = threadIdx.x, w = t >> 5, lane = t & 31;
    int g = lane >> 2, tg = lane & 3;
    int blk0 = blockIdx.x * 4;
    int mblk = w >> 1;
    int ocb  = (w & 1) * 64;

    float acc[4][8][4];
    #pragma unroll
    for (int mt = 0; mt < 4; mt++)
        #pragma unroll
        for (int nt = 0; nt < 8; nt++)
            #pragma unroll
            for (int e = 0; e < 4; e++) acc[mt][nt][e] = 0.0f;

    int xblk = t >> 6, xic = t & 63;

    for (int chunk = 0; chunk < 4; chunk++) {
        __syncthreads();
        {
            #pragma unroll
            for (int j = 0; j < 4; j++) {
                int idx = t + j * 256;
                int row = idx >> 3, q = idx & 7;
                const __half* gs = w316 + (size_t)chunk * 8192 + row * 64 + q * 8;
                uint32_t sd = sbase + W3OFF + row * X1STR + q * 16;
                cp_async16(sd, gs);
            }
            CP_COMMIT();
        }
        {
            int icg = chunk * 64 + xic;
            const float* src = g2buf + ((size_t)(blk0 + xblk) * C2 + icg) * 64;
            float a = d_a2[icg], bb = d_b2[icg];
            char* xb = smem + xblk * X3BLK + xic * 2;
            #pragma unroll
            for (int j = 0; j < 16; j++) {
                float4 v4 = ((const float4*)src)[j];
                float vals[4] = {v4.x, v4.y, v4.z, v4.w};
                #pragma unroll
                for (int e = 0; e < 4; e++) {
                    int px = j * 4 + e;
                    float xv = a * vals[e] + bb;
                    *(__half*)(xb + px * X1STR) = __float2half(xv);
                }
            }
        }
        CP_WAIT0();
        __syncthreads();

        const char* A  = smem + W3OFF;
        const char* Bh = smem + mblk * X3BLK;
        #pragma unroll
        for (int k4 = 0; k4 < 4; k4++) {
            int kb = (k4 * 16 + 2 * tg) * 2;
            unsigned af[4][4];
            #pragma unroll
            for (int mt = 0; mt < 4; mt++) {
                const char* ar = A + (ocb + mt * 16 + g) * X1STR + kb;
                af[mt][0] = *(const unsigned*)ar;
                af[mt][1] = *(const unsigned*)(ar + 8 * X1STR);
                af[mt][2] = *(const unsigned*)(ar + 16);
                af[mt][3] = *(const unsigned*)(ar + 8 * X1STR + 16);
            }
            #pragma unroll
            for (int nt = 0; nt < 8; nt++) {
                const char* br = Bh + (nt * 8 + g) * X1STR + kb;
                unsigned b0h = *(const unsigned*)br;
                unsigned b1h = *(const unsigned*)(br + 16);
                #pragma unroll
                for (int mt = 0; mt < 4; mt++)
                    mma16816h(acc[mt][nt], af[mt], b0h, b1h);
            }
        }
    }

    #pragma unroll
    for (int mt = 0; mt < 4; mt++) {
        int oc_a = ocb + mt * 16 + g;
        int oc_b = oc_a + 8;
        float ba = b3[oc_a], bbv = b3[oc_b];
        float* da = g3buf + ((size_t)(blk0 + mblk) * COUT + oc_a) * 64;
        float* db = g3buf + ((size_t)(blk0 + mblk) * COUT + oc_b) * 64;
        float sa = 0.f, qa = 0.f, sb = 0.f, qb = 0.f;
        #pragma unroll
        for (int nt = 0; nt < 8; nt++) {
            int n0 = nt * 8 + tg * 2;
            float2 e0, e1;
            e0.x = fmaxf(acc[mt][nt][0] + ba, 0.f);
            e0.y = fmaxf(acc[mt][nt][1] + ba, 0.f);
            e1.x = fmaxf(acc[mt][nt][2] + bbv, 0.f);
            e1.y = fmaxf(acc[mt][nt][3] + bbv, 0.f);
            sa += e0.x + e0.y; qa += e0.x * e0.x + e0.y * e0.y;
            sb += e1.x + e1.y; qb += e1.x * e1.x + e1.y * e1.y;
            *(float2*)(da + n0) = e0;
            *(float2*)(db + n0) = e1;
        }
        quad_stats(sa, qa, tg, &d_sum3[oc_a], &d_sq3[oc_a]);
        quad_stats(sb, qb, tg, &d_sum3[oc_b], &d_sq3[oc_b]);
    }
}

// ---------------- scatter: BN3(g3) -> image ----------------
__global__ __launch_bounds__(256) void scatter_kernel(const int* __restrict__ abi,
                                                      float* __restrict__ out) {
    int blk = blockIdx.x;
    int n  = abi[blk * 3 + 0];
    int bi = abi[blk * 3 + 1];
    int bj = abi[blk * 3 + 2];
    const float* src = g3buf + (size_t)blk * COUT * 64;
    float* dst = out + (((size_t)(n * COUT)) << 16) + bi * 8 * 256 + bj * 8;
    for (int i = threadIdx.x; i < 2048; i += 256) {
        int c = i >> 4, q = i & 15;
        int r = q >> 1, c4 = (q & 1) * 4;
        float4 v = *reinterpret_cast<const float4*>(src + c * 64 + q * 4);
        float a = d_a3[c], bb = d_b3[c];
        v.x = a * v.x + bb; v.y = a * v.y + bb;
        v.z = a * v.z + bb; v.w = a * v.w + bb;
        *reinterpret_cast<float4*>(dst + (((size_t)c) << 16) + r * 256 + c4) = v;
    }
}

// ---------------- launch ----------------
extern "C" void kernel_launch(void* const* d_in, const int* in_sizes, int n_in,
                              void* d_out, int out_size) {
    const float* x    = (const float*)d_in[0];
    const int*   abi  = (const int*)  d_in[1];
    const float* w_c  = (const float*)d_in[2];
    const float* b_c  = (const float*)d_in[3];
    const float* gm_c = (const float*)d_in[4];
    const float* be_c = (const float*)d_in[5];
    const float* w1   = (const float*)d_in[6];
    const float* b1   = (const float*)d_in[7];
    const float* gm1  = (const float*)d_in[8];
    const float* be1  = (const float*)d_in[9];
    const float* w2   = (const float*)d_in[10];
    const float* b2   = (const float*)d_in[11];
    const float* gm2  = (const float*)d_in[12];
    const float* be2  = (const float*)d_in[13];
    const float* w3   = (const float*)d_in[14];
    const float* b3   = (const float*)d_in[15];
    const float* gm3  = (const float*)d_in[16];
    const float* be3  = (const float*)d_in[17];
    float* out = (float*)d_out;

    static cudaStream_t s2 = nullptr;
    static cudaEvent_t evf = nullptr, evj = nullptr;
    if (s2 == nullptr) {
        cudaStreamCreateWithFlags(&s2, cudaStreamNonBlocking);
        cudaEventCreateWithFlags(&evf, cudaEventDisableTiming);
        cudaEventCreateWithFlags(&evj, cudaEventDisableTiming);
    }

    cudaFuncSetAttribute(convcm_kernel, cudaFuncAttributeMaxDynamicSharedMemorySize, SMEM_CCM);
    cudaFuncSetAttribute(conv1m_kernel, cudaFuncAttributeMaxDynamicSharedMemorySize, SMEM_C1M);
    cudaFuncSetAttribute(conv2m_kernel, cudaFuncAttributeMaxDynamicSharedMemorySize, SMEM_C2M);
    cudaFuncSetAttribute(conv3m_kernel, cudaFuncAttributeMaxDynamicSharedMemorySize, SMEM_C3M);

    zero_stats_kernel<<<1, 256>>>();
    w2cvt_kernel<<<576, 256>>>(w2);
    w13cvt_kernel<<<64, 256>>>(w1, w3, w_c);

    convcm_kernel<<<4096, 256, SMEM_CCM>>>(x, b_c, out);
    finalize_kernel<<<1, 256>>>(0, gm_c, be_c, 1.0 / 524288.0);

    conv1m_kernel<<<2048, 256, SMEM_C1M>>>(out, abi, b1);

    cudaEventRecord(evf, 0);
    cudaStreamWaitEvent(s2, evf, 0);
    bnapply_kernel<<<16384, 256, 0, s2>>>(out);
    cudaEventRecord(evj, s2);

    finalize_kernel<<<1, 256>>>(1, gm1, be1, 1.0 / 262144.0);

    conv2m_kernel<<<2048, 256, SMEM_C2M>>>(b2);
    finalize_kernel<<<1, 256>>>(2, gm2, be2, 1.0 / 262144.0);

    conv3m_kernel<<<1024, 256, SMEM_C3M>>>(b3);
    finalize_kernel<<<1, 256>>>(3, gm3, be3, 1.0 / 262144.0);

    cudaStreamWaitEvent(0, evj, 0);
    scatter_kernel<<<4096, 256>>>(abi, out);
}